// round 12
// baseline (speedup 1.0000x reference)
#include <cuda_runtime.h>
#include <cuda_bf16.h>
#include <math.h>
#include <stdint.h>

#define BB    4
#define NPTS  8192
#define SPTS  2048
#define D1C   128
#define D2C   256
#define CIN   384
#define CMID  256
#define COUT  256
#define BNT   (BB*NPTS)     // 32768
#define KP1   (3*CIN)       // 1152
#define KP2   (3*CMID)      // 768
#define KCH1  (KP1/64)      // 18
#define KCH2  (KP2/64)      // 12

// ---------------- scratch (device globals) ----------------
__device__ __align__(256) float          g_f2t[BB*SPTS*D2C];          // [B,S,D2]
__device__ __align__(256) __nv_bfloat16  g_featB[(size_t)BNT*KP1];    // B op GEMM1
__device__ __align__(256) __nv_bfloat16  g_W1e[CMID*KP1];             // A op GEMM1
__device__ __align__(256) __nv_bfloat16  g_W2e[COUT*KP2];             // A op GEMM2
__device__ __align__(256) float          g_y1T[(size_t)BNT*CMID];     // y1 pre-BN
__device__ __align__(256) __nv_bfloat16  g_y2B[(size_t)BNT*KP2];      // B op GEMM2
__device__ int   g_idx[BNT*3];
__device__ float g_w[BNT*3];
__device__ float g_sum1[CMID], g_sq1[CMID], g_sum2[COUT], g_sq2[COUT];

// ---------------- small helpers ----------------
__device__ __forceinline__ void cp16(uint32_t dst, const void* src){
    asm volatile("cp.async.cg.shared.global [%0], [%1], 16;" :: "r"(dst), "l"(src));
}
__device__ __forceinline__ void ldm4(uint32_t* r, uint32_t addr){
    asm volatile("ldmatrix.sync.aligned.m8n8.x4.shared.b16 {%0,%1,%2,%3}, [%4];"
        : "=r"(r[0]), "=r"(r[1]), "=r"(r[2]), "=r"(r[3]) : "r"(addr));
}
__device__ __forceinline__ void mma16816(float* d, const uint32_t* a, uint32_t b0, uint32_t b1){
    asm volatile(
        "mma.sync.aligned.m16n8k16.row.col.f32.bf16.bf16.f32 "
        "{%0,%1,%2,%3}, {%4,%5,%6,%7}, {%8,%9}, {%0,%1,%2,%3};"
        : "+f"(d[0]), "+f"(d[1]), "+f"(d[2]), "+f"(d[3])
        : "r"(a[0]), "r"(a[1]), "r"(a[2]), "r"(a[3]), "r"(b0), "r"(b1));
}

__device__ __forceinline__ void split_bf(float v, uint32_t& hi, uint32_t& lo){
    __nv_bfloat16 h = __float2bfloat16(v);
    float r = v - __bfloat162float(h);
    __nv_bfloat16 l = __float2bfloat16(r);
    hi = (uint32_t)__bfloat16_as_ushort(h);
    lo = (uint32_t)__bfloat16_as_ushort(l);
}

// B-side pattern per channel: [hi, lo, hi]; packs 4 channels -> 6 uint32
__device__ __forceinline__ void packB4(const float* v, uint32_t* u){
    uint32_t h[4], l[4];
    #pragma unroll
    for (int j = 0; j < 4; j++) split_bf(v[j], h[j], l[j]);
    u[0] = h[0] | (l[0] << 16);
    u[1] = h[0] | (h[1] << 16);
    u[2] = l[1] | (h[1] << 16);
    u[3] = h[2] | (l[2] << 16);
    u[4] = h[2] | (h[3] << 16);
    u[5] = l[3] | (h[3] << 16);
}

__device__ __forceinline__ void store_pack8(void* dst, const float* v){
    uint32_t u[12];
    packB4(v, u); packB4(v + 4, u + 6);
    uint4* d4 = (uint4*)dst;
    d4[0] = make_uint4(u[0], u[1], u[2],  u[3]);
    d4[1] = make_uint4(u[4], u[5], u[6],  u[7]);
    d4[2] = make_uint4(u[8], u[9], u[10], u[11]);
}

// ============================================================
// 3-NN: two independent candidate streams for ILP, merged at end.
// (block (0,0) also zeroes BN accumulators)
// ============================================================
#define KNN_INS(dv,iv,d0,i0,d1,i1,d2,i2)                          \
    if ((dv) < (d2)) {                                            \
        if ((dv) < (d1)) {                                        \
            d2 = d1; i2 = i1;                                     \
            if ((dv) < (d0)) { d1 = d0; i1 = i0; d0 = dv; i0 = iv; } \
            else             { d1 = dv; i1 = iv; }                \
        } else { d2 = dv; i2 = iv; }                              \
    }

__global__ void knn_kernel(const float* __restrict__ pos1,
                           const float* __restrict__ pos2) {
    __shared__ float4 sp[SPTS];
    int b = blockIdx.y;
    if (blockIdx.x == 0 && blockIdx.y == 0) {
        int t = threadIdx.x;
        g_sum1[t] = 0.f; g_sq1[t] = 0.f; g_sum2[t] = 0.f; g_sq2[t] = 0.f;
    }
    const float* p2 = pos2 + (size_t)b*3*SPTS;
    for (int s = threadIdx.x; s < SPTS; s += blockDim.x) {
        float x = p2[s], y = p2[SPTS+s], z = p2[2*SPTS+s];
        sp[s] = make_float4(x, y, z, x*x+y*y+z*z);
    }
    __syncthreads();

    int n = blockIdx.x*blockDim.x + threadIdx.x;
    const float* p1 = pos1 + (size_t)b*3*NPTS;
    float px = p1[n], py = p1[NPTS+n], pz = p1[2*NPTS+n];
    float n1 = px*px+py*py+pz*pz;

    // stream A: s in [0,1024), stream B: [1024,2048)
    float d0a=1e30f, d1a=1e30f, d2a=1e30f; int i0a=0, i1a=0, i2a=0;
    float d0b=1e30f, d1b=1e30f, d2b=1e30f; int i0b=1024, i1b=1024, i2b=1024;
    #pragma unroll 2
    for (int s = 0; s < 1024; s++) {
        float4 ca = sp[s];
        float da = n1 - 2.0f*(px*ca.x + py*ca.y + pz*ca.z) + ca.w;
        float4 cb = sp[s + 1024];
        float db = n1 - 2.0f*(px*cb.x + py*cb.y + pz*cb.z) + cb.w;
        KNN_INS(da, s,        d0a,i0a, d1a,i1a, d2a,i2a);
        KNN_INS(db, s + 1024, d0b,i0b, d1b,i1b, d2b,i2b);
    }
    // merge B into A (strict < keeps A priority on ties; A indices are lower)
    KNN_INS(d0b, i0b, d0a,i0a, d1a,i1a, d2a,i2a);
    KNN_INS(d1b, i1b, d0a,i0a, d1a,i1a, d2a,i2a);
    KNN_INS(d2b, i2b, d0a,i0a, d1a,i1a, d2a,i2a);

    float a0 = fmaxf(d0a, 1e-10f), a1 = fmaxf(d1a, 1e-10f), a2 = fmaxf(d2a, 1e-10f);
    float w0 = 1.0f/a0, w1 = 1.0f/a1, w2 = 1.0f/a2;
    float inv = 1.0f/(w0+w1+w2);
    int base = (b*NPTS + n)*3;
    g_idx[base+0]=i0a; g_idx[base+1]=i1a; g_idx[base+2]=i2a;
    g_w[base+0]=w0*inv; g_w[base+1]=w1*inv; g_w[base+2]=w2*inv;
}

// ============================================================
// feature2 [B,D2,S] -> g_f2t [B,S,D2]
// ============================================================
__global__ void transpose_f2(const float* __restrict__ f2) {
    __shared__ float t[32][33];
    int b = blockIdx.z;
    int d0 = blockIdx.y*32, s0 = blockIdx.x*32;
    int lx = threadIdx.x, ly = threadIdx.y;
    const float* src = f2 + (size_t)b*D2C*SPTS;
    #pragma unroll
    for (int i = ly; i < 32; i += 8)
        t[i][lx] = src[(size_t)(d0+i)*SPTS + s0 + lx];
    __syncthreads();
    float* dst = g_f2t + (size_t)b*SPTS*D2C;
    #pragma unroll
    for (int i = ly; i < 32; i += 8)
        dst[(size_t)(s0+i)*D2C + d0 + lx] = t[lx][i];
}

// ============================================================
// interp: weighted 3-NN -> g_featB rows k'=[0, 3*D2)
// ============================================================
__global__ void interp_kernel() {
    int t = threadIdx.x;
    int p = blockIdx.x*8 + (t >> 5);
    int kg = t & 31;
    int i0 = __ldg(&g_idx[p*3+0]), i1 = __ldg(&g_idx[p*3+1]), i2 = __ldg(&g_idx[p*3+2]);
    float w0 = __ldg(&g_w[p*3+0]), w1 = __ldg(&g_w[p*3+1]), w2 = __ldg(&g_w[p*3+2]);
    int b = p >> 13;
    const float* f2 = g_f2t + (size_t)b*SPTS*D2C;
    int k0 = kg*8;
    float v[8];
    #pragma unroll
    for (int h = 0; h < 2; h++) {
        float4 a = *(const float4*)&f2[(size_t)i0*D2C + k0 + h*4];
        float4 c = *(const float4*)&f2[(size_t)i1*D2C + k0 + h*4];
        float4 d = *(const float4*)&f2[(size_t)i2*D2C + k0 + h*4];
        v[h*4+0] = w0*a.x + w1*c.x + w2*d.x;
        v[h*4+1] = w0*a.y + w1*c.y + w2*d.y;
        v[h*4+2] = w0*a.z + w1*c.z + w2*d.z;
        v[h*4+3] = w0*a.w + w1*c.w + w2*d.w;
    }
    store_pack8((char*)g_featB + (size_t)p*KP1*2 + (size_t)k0*6, v);
}

// ============================================================
// feature1 [B,D1,N] -> g_featB rows k'=[3*D2, 3*CIN)
// ============================================================
__global__ void copy_f1(const float* __restrict__ f1) {
    __shared__ float tile[64][33];
    int b = blockIdx.z, d0 = blockIdx.y*64, n0 = blockIdx.x*32;
    int t = threadIdx.x;
    int lx = t & 31, ly = t >> 5;
    const float* src = f1 + ((size_t)b*D1C + d0)*NPTS + n0;
    #pragma unroll
    for (int i = ly; i < 64; i += 8)
        tile[i][lx] = src[(size_t)i*NPTS + lx];
    __syncthreads();
    int g = t & 7, nn = t >> 3;
    int n = b*NPTS + n0 + nn;
    int d = d0 + g*8;
    float v[8];
    #pragma unroll
    for (int j = 0; j < 8; j++) v[j] = tile[g*8+j][nn];
    store_pack8((char*)g_featB + (size_t)n*KP1*2 + (size_t)(D2C + d)*6, v);
}

// ============================================================
// weight expand (both layers): A pattern [hi, hi, lo]
// ============================================================
__global__ void wexpand_all(const float* __restrict__ W1,
                            const float* __restrict__ W2) {
    int i = blockIdx.x*blockDim.x + threadIdx.x;
    float v; __nv_bfloat16* p;
    if (i < CMID*CIN) {
        int m = i / CIN, k = i - m*CIN;
        v = W1[i];
        p = g_W1e + (size_t)m*KP1 + 3*k;
    } else {
        int j = i - CMID*CIN;
        int m = j / CMID, k = j - m*CMID;
        v = W2[j];
        p = g_W2e + (size_t)m*KP2 + 3*k;
    }
    uint32_t hi, lo; split_bf(v, hi, lo);
    p[0] = __ushort_as_bfloat16((unsigned short)hi);
    p[1] = __ushort_as_bfloat16((unsigned short)hi);
    p[2] = __ushort_as_bfloat16((unsigned short)lo);
}

// ============================================================
// mma.sync GEMM: CTA 256m x 128n x 64k, 8 warps (4m x 2n), warp 64x64.
// 4-stage cp.async pipeline, single __syncthreads per chunk.
// Bias folded into acc; BN sums shuffle-reduced from acc + atomics.
// MODE 0: store y1 point-major (via [n][m] stage).
// MODE 1: store pre-BN y2 directly to out [B,C,N] (via [m][n] stage).
// ============================================================
#define STAGE_BYTES 49152            // A 32KB + B 16KB
#define SMEM_DYN    (4*STAGE_BYTES + 128)

template<int Kp>
__device__ __forceinline__ void load_chunk(uint32_t sA, uint32_t sB,
        const __nv_bfloat16* __restrict__ A, const __nv_bfloat16* __restrict__ B,
        int n0, int c, int t) {
    int seg = t & 7, r0 = t >> 3;
    const char* Ab = (const char*)A + ((size_t)c*64)*2 + (size_t)seg*16;
    const char* Bb = (const char*)B + ((size_t)n0*Kp + c*64)*2 + (size_t)seg*16;
    #pragma unroll
    for (int i = 0; i < 8; i++) {
        int row = r0 + i*32;
        uint32_t sw = (uint32_t)(seg ^ (row & 7))*16u;
        cp16(sA + row*128 + sw, Ab + (size_t)row*Kp*2);
    }
    #pragma unroll
    for (int i = 0; i < 4; i++) {
        int row = r0 + i*32;
        uint32_t sw = (uint32_t)(seg ^ (row & 7))*16u;
        cp16(sB + row*128 + sw, Bb + (size_t)row*Kp*2);
    }
    asm volatile("cp.async.commit_group;" ::: "memory");
}

template<int MODE>
__global__ void __launch_bounds__(256)
mma_gemm(const float* __restrict__ bias, float* __restrict__ out_ext) {
    constexpr int KCH = (MODE == 0) ? KCH1 : KCH2;
    constexpr int Kp  = KCH*64;
    const __nv_bfloat16* A = (MODE == 0) ? g_W1e  : g_W2e;
    const __nv_bfloat16* B = (MODE == 0) ? g_featB : g_y2B;
    float* sacc = (MODE == 0) ? g_sum1 : g_sum2;
    float* qacc = (MODE == 0) ? g_sq1  : g_sq2;

    extern __shared__ char smem[];
    uint32_t sb;
    asm("{ .reg .u64 t; cvta.to.shared.u64 t, %1; cvt.u32.u64 %0, t; }"
        : "=r"(sb) : "l"(smem));
    uint32_t base = (sb + 127u) & ~127u;
    float* stage = (float*)(smem + (base - sb));

    int t = threadIdx.x, wid = t >> 5, lane = t & 31;
    int wm = wid >> 1, wn = wid & 1;
    int n0 = blockIdx.x*128;
    int m0w = wm*64, n0w = wn*64;

    float acc[4][8][4];
    #pragma unroll
    for (int i = 0; i < 4; i++)
        #pragma unroll
        for (int j = 0; j < 8; j++)
            #pragma unroll
            for (int e = 0; e < 4; e++) acc[i][j][e] = 0.f;

    int laneRow = lane & 15, laneHi = lane >> 4;
    int q = lane & 3, r = lane >> 2;

    load_chunk<Kp>(base + 0*STAGE_BYTES, base + 0*STAGE_BYTES + 32768, A, B, n0, 0, t);
    load_chunk<Kp>(base + 1*STAGE_BYTES, base + 1*STAGE_BYTES + 32768, A, B, n0, 1, t);
    load_chunk<Kp>(base + 2*STAGE_BYTES, base + 2*STAGE_BYTES + 32768, A, B, n0, 2, t);

    int bi = 0;
    for (int c = 0; c < KCH; c++) {
        int w = KCH - 1 - c;
        if (w >= 2)      asm volatile("cp.async.wait_group 2;" ::: "memory");
        else if (w == 1) asm volatile("cp.async.wait_group 1;" ::: "memory");
        else             asm volatile("cp.async.wait_group 0;" ::: "memory");
        __syncthreads();
        uint32_t curA = base + bi*STAGE_BYTES;
        uint32_t curB = curA + 32768;

        #pragma unroll
        for (int ks = 0; ks < 4; ks++) {
            int seg = 2*ks + laneHi;
            uint32_t a[4][4], b[4][4];
            #pragma unroll
            for (int mi = 0; mi < 4; mi++) {
                int row = m0w + 16*mi + laneRow;
                ldm4(a[mi], curA + row*128 + (uint32_t)(seg ^ (row & 7))*16u);
            }
            #pragma unroll
            for (int nj = 0; nj < 4; nj++) {
                int row = n0w + 16*nj + laneRow;
                ldm4(b[nj], curB + row*128 + (uint32_t)(seg ^ (row & 7))*16u);
            }
            #pragma unroll
            for (int mi = 0; mi < 4; mi++)
                #pragma unroll
                for (int f = 0; f < 8; f++)
                    mma16816(acc[mi][f], a[mi], b[f>>1][f&1], b[f>>1][(f&1)+2]);
        }
        if (c + 3 < KCH) {
            uint32_t nb = base + ((bi + 3) & 3)*STAGE_BYTES;
            load_chunk<Kp>(nb, nb + 32768, A, B, n0, c + 3, t);
        }
        bi = (bi + 1) & 3;
    }

    // ---- fold bias into acc ----
    #pragma unroll
    for (int mi = 0; mi < 4; mi++) {
        float b0 = __ldg(&bias[m0w + 16*mi + r]);
        float b8 = __ldg(&bias[m0w + 16*mi + 8 + r]);
        #pragma unroll
        for (int f = 0; f < 8; f++) {
            acc[mi][f][0] += b0; acc[mi][f][1] += b0;
            acc[mi][f][2] += b8; acc[mi][f][3] += b8;
        }
    }

    // ---- BN sums from registers: reduce over this warp's 64 n-columns ----
    #pragma unroll
    for (int mi = 0; mi < 4; mi++) {
        #pragma unroll
        for (int h = 0; h < 2; h++) {
            float s = 0.f, qq = 0.f;
            #pragma unroll
            for (int f = 0; f < 8; f++) {
                float v0 = acc[mi][f][h*2+0], v1 = acc[mi][f][h*2+1];
                s += v0 + v1; qq += v0*v0 + v1*v1;
            }
            s  += __shfl_xor_sync(0xFFFFFFFFu, s, 1);
            s  += __shfl_xor_sync(0xFFFFFFFFu, s, 2);
            qq += __shfl_xor_sync(0xFFFFFFFFu, qq, 1);
            qq += __shfl_xor_sync(0xFFFFFFFFu, qq, 2);
            if (q == 0) {
                int m = m0w + 16*mi + 8*h + r;
                atomicAdd(&sacc[m], s);
                atomicAdd(&qacc[m], qq);
            }
        }
    }

    __syncthreads();   // operand smem -> stage reuse

    if (MODE == 0) {
        // stage [n(128)][m(256)], pad 260
        #pragma unroll
        for (int mi = 0; mi < 4; mi++) {
            int m_l = m0w + 16*mi + r;
            #pragma unroll
            for (int f = 0; f < 8; f++) {
                int n_l = n0w + 8*f + 2*q;
                stage[(size_t)n_l*260 + m_l]          = acc[mi][f][0];
                stage[(size_t)(n_l+1)*260 + m_l]      = acc[mi][f][1];
                stage[(size_t)n_l*260 + m_l + 8]      = acc[mi][f][2];
                stage[(size_t)(n_l+1)*260 + m_l + 8]  = acc[mi][f][3];
            }
        }
        __syncthreads();
        #pragma unroll 4
        for (int idx = t; idx < 128*64; idx += 256) {
            int n_l = idx >> 6, m4 = idx & 63;
            float4 v = *(float4*)&stage[(size_t)n_l*260 + m4*4];
            *(float4*)&g_y1T[(size_t)(n0 + n_l)*256 + m4*4] = v;
        }
    } else {
        // stage [m(256)][n(128)], pad 132
        #pragma unroll
        for (int mi = 0; mi < 4; mi++) {
            int m_l = m0w + 16*mi + r;
            #pragma unroll
            for (int f = 0; f < 8; f++) {
                int n_l = n0w + 8*f + 2*q;
                *(float2*)&stage[(size_t)m_l*132 + n_l]     = make_float2(acc[mi][f][0], acc[mi][f][1]);
                *(float2*)&stage[(size_t)(m_l+8)*132 + n_l] = make_float2(acc[mi][f][2], acc[mi][f][3]);
            }
        }
        __syncthreads();
        int bb = n0 >> 13, nn0 = n0 & (NPTS-1);
        float* obase = out_ext + (size_t)bb*COUT*NPTS + nn0;
        #pragma unroll 4
        for (int idx = t; idx < 256*32; idx += 256) {
            int n4 = idx & 31, m = idx >> 5;
            float4 v = *(float4*)&stage[(size_t)m*132 + n4*4];
            *(float4*)&obase[(size_t)m*NPTS + n4*4] = v;
        }
    }
}

// ============================================================
// prep2: BN1 affine in-block, relu(bn1(y1)) -> split bf16 B operand
// ============================================================
__global__ void prep2(const float* __restrict__ g, const float* __restrict__ beta) {
    __shared__ float ssc[CMID], ssh[CMID];
    int t = threadIdx.x;
    {
        float mean = g_sum1[t] * (1.0f/(float)BNT);
        float var  = g_sq1[t]  * (1.0f/(float)BNT) - mean*mean;
        float r = rsqrtf(var + 1e-5f);
        float sc = g[t]*r;
        ssc[t] = sc;
        ssh[t] = beta[t] - mean*sc;
    }
    __syncthreads();
    int gi = blockIdx.x*256 + t;
    int n = gi >> 5, kg = gi & 31, k0 = kg*8;
    float v[8];
    #pragma unroll
    for (int h = 0; h < 2; h++) {
        float4 y = *(const float4*)&g_y1T[(size_t)n*CMID + k0 + h*4];
        int kb = k0 + h*4;
        v[h*4+0] = fmaxf(y.x*ssc[kb+0] + ssh[kb+0], 0.f);
        v[h*4+1] = fmaxf(y.y*ssc[kb+1] + ssh[kb+1], 0.f);
        v[h*4+2] = fmaxf(y.z*ssc[kb+2] + ssh[kb+2], 0.f);
        v[h*4+3] = fmaxf(y.w*ssc[kb+3] + ssh[kb+3], 0.f);
    }
    store_pack8((char*)g_y2B + (size_t)n*KP2*2 + (size_t)k0*6, v);
}

// ============================================================
// final: streaming in-place BN2 + ReLU on out [B,C,N]
// ============================================================
__global__ void final_bn(float* __restrict__ out,
                         const float* __restrict__ g, const float* __restrict__ beta) {
    __shared__ float ssc[COUT], ssh[COUT];
    int t = threadIdx.x;
    {
        float mean = g_sum2[t] * (1.0f/(float)BNT);
        float var  = g_sq2[t]  * (1.0f/(float)BNT) - mean*mean;
        float r = rsqrtf(var + 1e-5f);
        float sc = g[t]*r;
        ssc[t] = sc;
        ssh[t] = beta[t] - mean*sc;
    }
    __syncthreads();
    float4* o4 = (float4*)out;
    size_t base = (size_t)blockIdx.x*1024 + t;
    #pragma unroll
    for (int rr = 0; rr < 4; rr++) {
        size_t i4 = base + (size_t)rr*256;
        int o = (int)((i4 >> 11) & 255);
        float4 v = o4[i4];
        float sc = ssc[o], sh = ssh[o];
        v.x = fmaxf(v.x*sc + sh, 0.f);
        v.y = fmaxf(v.y*sc + sh, 0.f);
        v.z = fmaxf(v.z*sc + sh, 0.f);
        v.w = fmaxf(v.w*sc + sh, 0.f);
        o4[i4] = v;
    }
}

// ============================================================
extern "C" void kernel_launch(void* const* d_in, const int* in_sizes, int n_in,
                              void* d_out, int out_size) {
    const float* pos1 = (const float*)d_in[0];
    const float* pos2 = (const float*)d_in[1];
    const float* f1   = (const float*)d_in[2];
    const float* f2   = (const float*)d_in[3];
    const float* W1   = (const float*)d_in[4];
    const float* b1   = (const float*)d_in[5];
    const float* g1   = (const float*)d_in[6];
    const float* be1  = (const float*)d_in[7];
    const float* W2   = (const float*)d_in[8];
    const float* b2   = (const float*)d_in[9];
    const float* g2   = (const float*)d_in[10];
    const float* be2  = (const float*)d_in[11];
    float* out = (float*)d_out;

    cudaFuncSetAttribute(mma_gemm<0>, cudaFuncAttributeMaxDynamicSharedMemorySize, SMEM_DYN);
    cudaFuncSetAttribute(mma_gemm<1>, cudaFuncAttributeMaxDynamicSharedMemorySize, SMEM_DYN);

    knn_kernel   <<<dim3(NPTS/256, BB), 256>>>(pos1, pos2);
    transpose_f2 <<<dim3(SPTS/32, D2C/32, BB), dim3(32,8)>>>(f2);
    interp_kernel<<<BNT/8, 256>>>();
    copy_f1      <<<dim3(NPTS/32, D1C/64, BB), 256>>>(f1);
    wexpand_all  <<<(CMID*CIN + COUT*CMID)/256, 256>>>(W1, W2);

    mma_gemm<0>  <<<BNT/128, 256, SMEM_DYN>>>(b1, nullptr);
    prep2        <<<(BNT*32)/256, 256>>>(g1, be1);
    mma_gemm<1>  <<<BNT/128, 256, SMEM_DYN>>>(b2, out);
    final_bn     <<<(BB*COUT*NPTS)/4096, 256>>>(out, g2, be2);
}

// round 13
// speedup vs baseline: 1.0562x; 1.0562x over previous
#include <cuda_runtime.h>
#include <cuda_bf16.h>
#include <math.h>
#include <stdint.h>

#define BB    4
#define NPTS  8192
#define SPTS  2048
#define D1C   128
#define D2C   256
#define CIN   384
#define CMID  256
#define COUT  256
#define BNT   (BB*NPTS)     // 32768
#define KH1   (2*CIN)       // 768 bf16 per point (hi|lo blocks of 64)
#define KH2   (2*CMID)      // 512
#define SC1   (CIN/64)      // 6 super-chunks
#define SC2   (CMID/64)     // 4

// ---------------- scratch (device globals) ----------------
__device__ __align__(256) float          g_f2t[BB*SPTS*D2C];          // [B,S,D2]
__device__ __align__(256) __nv_bfloat16  g_featB[(size_t)BNT*KH1];    // B op GEMM1 (hi|lo)
__device__ __align__(256) __nv_bfloat16  g_W1e[CMID*KH1];             // A op GEMM1 (hi|lo)
__device__ __align__(256) __nv_bfloat16  g_W2e[COUT*KH2];             // A op GEMM2 (hi|lo)
__device__ __align__(256) float          g_y1T[(size_t)BNT*CMID];     // y1 pre-BN, point-major
__device__ __align__(256) __nv_bfloat16  g_y2B[(size_t)BNT*KH2];      // B op GEMM2 (hi|lo)
__device__ __align__(256) float          g_y2T[(size_t)BNT*COUT];     // y2 pre-BN, point-major
__device__ int   g_idx[BNT*3];
__device__ float g_w[BNT*3];
__device__ float g_sum1[CMID], g_sq1[CMID], g_sum2[COUT], g_sq2[COUT];

// ---------------- small helpers ----------------
__device__ __forceinline__ void cp16(uint32_t dst, const void* src){
    asm volatile("cp.async.cg.shared.global [%0], [%1], 16;" :: "r"(dst), "l"(src));
}
__device__ __forceinline__ void ldm4(uint32_t* r, uint32_t addr){
    asm volatile("ldmatrix.sync.aligned.m8n8.x4.shared.b16 {%0,%1,%2,%3}, [%4];"
        : "=r"(r[0]), "=r"(r[1]), "=r"(r[2]), "=r"(r[3]) : "r"(addr));
}
__device__ __forceinline__ void mma16816(float* d, const uint32_t* a, uint32_t b0, uint32_t b1){
    asm volatile(
        "mma.sync.aligned.m16n8k16.row.col.f32.bf16.bf16.f32 "
        "{%0,%1,%2,%3}, {%4,%5,%6,%7}, {%8,%9}, {%0,%1,%2,%3};"
        : "+f"(d[0]), "+f"(d[1]), "+f"(d[2]), "+f"(d[3])
        : "r"(a[0]), "r"(a[1]), "r"(a[2]), "r"(a[3]), "r"(b0), "r"(b1));
}

__device__ __forceinline__ void split_bf(float v, uint32_t& hi, uint32_t& lo){
    __nv_bfloat16 h = __float2bfloat16(v);
    float r = v - __bfloat162float(h);
    __nv_bfloat16 l = __float2bfloat16(r);
    hi = (uint32_t)__bfloat16_as_ushort(h);
    lo = (uint32_t)__bfloat16_as_ushort(l);
}

// 8 consecutive channels -> hi uint4 + lo uint4 (16B each, aligned)
__device__ __forceinline__ void store_packHL8(void* dhi, void* dlo, const float* v){
    uint32_t h[8], l[8];
    #pragma unroll
    for (int j = 0; j < 8; j++) split_bf(v[j], h[j], l[j]);
    *(uint4*)dhi = make_uint4(h[0]|(h[1]<<16), h[2]|(h[3]<<16), h[4]|(h[5]<<16), h[6]|(h[7]<<16));
    *(uint4*)dlo = make_uint4(l[0]|(l[1]<<16), l[2]|(l[3]<<16), l[4]|(l[5]<<16), l[6]|(l[7]<<16));
}

// smem addr within a 256B-row tile, SW within each 128B half
__device__ __forceinline__ uint32_t swz256(int row, int o){
    return (uint32_t)(row*256 + (o & 128) + ((o & 127) ^ ((row & 7)*16)));
}

// ============================================================
// 3-NN: two independent candidate streams for ILP, merged at end.
// (block (0,0) also zeroes BN accumulators)
// ============================================================
#define KNN_INS(dv,iv,d0,i0,d1,i1,d2,i2)                          \
    if ((dv) < (d2)) {                                            \
        if ((dv) < (d1)) {                                        \
            d2 = d1; i2 = i1;                                     \
            if ((dv) < (d0)) { d1 = d0; i1 = i0; d0 = dv; i0 = iv; } \
            else             { d1 = dv; i1 = iv; }                \
        } else { d2 = dv; i2 = iv; }                              \
    }

__global__ void knn_kernel(const float* __restrict__ pos1,
                           const float* __restrict__ pos2) {
    __shared__ float4 sp[SPTS];
    int b = blockIdx.y;
    if (blockIdx.x == 0 && blockIdx.y == 0) {
        int t = threadIdx.x;
        g_sum1[t] = 0.f; g_sq1[t] = 0.f; g_sum2[t] = 0.f; g_sq2[t] = 0.f;
    }
    const float* p2 = pos2 + (size_t)b*3*SPTS;
    for (int s = threadIdx.x; s < SPTS; s += blockDim.x) {
        float x = p2[s], y = p2[SPTS+s], z = p2[2*SPTS+s];
        sp[s] = make_float4(x, y, z, x*x+y*y+z*z);
    }
    __syncthreads();

    int n = blockIdx.x*blockDim.x + threadIdx.x;
    const float* p1 = pos1 + (size_t)b*3*NPTS;
    float px = p1[n], py = p1[NPTS+n], pz = p1[2*NPTS+n];
    float n1 = px*px+py*py+pz*pz;

    float d0a=1e30f, d1a=1e30f, d2a=1e30f; int i0a=0, i1a=0, i2a=0;
    float d0b=1e30f, d1b=1e30f, d2b=1e30f; int i0b=1024, i1b=1024, i2b=1024;
    #pragma unroll 2
    for (int s = 0; s < 1024; s++) {
        float4 ca = sp[s];
        float da = n1 - 2.0f*(px*ca.x + py*ca.y + pz*ca.z) + ca.w;
        float4 cb = sp[s + 1024];
        float db = n1 - 2.0f*(px*cb.x + py*cb.y + pz*cb.z) + cb.w;
        KNN_INS(da, s,        d0a,i0a, d1a,i1a, d2a,i2a);
        KNN_INS(db, s + 1024, d0b,i0b, d1b,i1b, d2b,i2b);
    }
    KNN_INS(d0b, i0b, d0a,i0a, d1a,i1a, d2a,i2a);
    KNN_INS(d1b, i1b, d0a,i0a, d1a,i1a, d2a,i2a);
    KNN_INS(d2b, i2b, d0a,i0a, d1a,i1a, d2a,i2a);

    float a0 = fmaxf(d0a, 1e-10f), a1 = fmaxf(d1a, 1e-10f), a2 = fmaxf(d2a, 1e-10f);
    float w0 = 1.0f/a0, w1 = 1.0f/a1, w2 = 1.0f/a2;
    float inv = 1.0f/(w0+w1+w2);
    int base = (b*NPTS + n)*3;
    g_idx[base+0]=i0a; g_idx[base+1]=i1a; g_idx[base+2]=i2a;
    g_w[base+0]=w0*inv; g_w[base+1]=w1*inv; g_w[base+2]=w2*inv;
}

// ============================================================
// feature2 [B,D2,S] -> g_f2t [B,S,D2]
// ============================================================
__global__ void transpose_f2(const float* __restrict__ f2) {
    __shared__ float t[32][33];
    int b = blockIdx.z;
    int d0 = blockIdx.y*32, s0 = blockIdx.x*32;
    int lx = threadIdx.x, ly = threadIdx.y;
    const float* src = f2 + (size_t)b*D2C*SPTS;
    #pragma unroll
    for (int i = ly; i < 32; i += 8)
        t[i][lx] = src[(size_t)(d0+i)*SPTS + s0 + lx];
    __syncthreads();
    float* dst = g_f2t + (size_t)b*SPTS*D2C;
    #pragma unroll
    for (int i = ly; i < 32; i += 8)
        dst[(size_t)(s0+i)*D2C + d0 + lx] = t[lx][i];
}

// ============================================================
// interp: weighted 3-NN -> g_featB channels [0, D2) as hi|lo blocks
// ============================================================
__global__ void interp_kernel() {
    int t = threadIdx.x;
    int p = blockIdx.x*8 + (t >> 5);
    int kg = t & 31;
    int i0 = __ldg(&g_idx[p*3+0]), i1 = __ldg(&g_idx[p*3+1]), i2 = __ldg(&g_idx[p*3+2]);
    float w0 = __ldg(&g_w[p*3+0]), w1 = __ldg(&g_w[p*3+1]), w2 = __ldg(&g_w[p*3+2]);
    int b = p >> 13;
    const float* f2 = g_f2t + (size_t)b*SPTS*D2C;
    int k0 = kg*8;
    float v[8];
    #pragma unroll
    for (int h = 0; h < 2; h++) {
        float4 a = *(const float4*)&f2[(size_t)i0*D2C + k0 + h*4];
        float4 c = *(const float4*)&f2[(size_t)i1*D2C + k0 + h*4];
        float4 d = *(const float4*)&f2[(size_t)i2*D2C + k0 + h*4];
        v[h*4+0] = w0*a.x + w1*c.x + w2*d.x;
        v[h*4+1] = w0*a.y + w1*c.y + w2*d.y;
        v[h*4+2] = w0*a.z + w1*c.z + w2*d.z;
        v[h*4+3] = w0*a.w + w1*c.w + w2*d.w;
    }
    char* base = (char*)g_featB + (size_t)p*KH1*2 + (size_t)(k0>>6)*256 + (size_t)(k0&63)*2;
    store_packHL8(base, base + 128, v);
}

// ============================================================
// feature1 [B,D1,N] -> g_featB channels [D2, CIN) as hi|lo blocks
// ============================================================
__global__ void copy_f1(const float* __restrict__ f1) {
    __shared__ float tile[64][33];
    int b = blockIdx.z, d0 = blockIdx.y*64, n0 = blockIdx.x*32;
    int t = threadIdx.x;
    int lx = t & 31, ly = t >> 5;
    const float* src = f1 + ((size_t)b*D1C + d0)*NPTS + n0;
    #pragma unroll
    for (int i = ly; i < 64; i += 8)
        tile[i][lx] = src[(size_t)i*NPTS + lx];
    __syncthreads();
    int g = t & 7, nn = t >> 3;
    int n = b*NPTS + n0 + nn;
    int c = D2C + d0 + g*8;   // global channel
    float v[8];
    #pragma unroll
    for (int j = 0; j < 8; j++) v[j] = tile[g*8+j][nn];
    char* base = (char*)g_featB + (size_t)n*KH1*2 + (size_t)(c>>6)*256 + (size_t)(c&63)*2;
    store_packHL8(base, base + 128, v);
}

// ============================================================
// weight expand (both layers): hi|lo blocks of 64 channels
// ============================================================
__global__ void wexpand_all(const float* __restrict__ W1,
                            const float* __restrict__ W2) {
    int i = blockIdx.x*blockDim.x + threadIdx.x;
    float v; __nv_bfloat16* p;
    if (i < CMID*CIN) {
        int m = i / CIN, k = i - m*CIN;
        v = W1[i];
        p = g_W1e + (size_t)m*KH1 + (k>>6)*128 + (k&63);
    } else {
        int j = i - CMID*CIN;
        int m = j / CMID, k = j - m*CMID;
        v = W2[j];
        p = g_W2e + (size_t)m*KH2 + (k>>6)*128 + (k&63);
    }
    uint32_t hi, lo; split_bf(v, hi, lo);
    p[0]  = __ushort_as_bfloat16((unsigned short)hi);
    p[64] = __ushort_as_bfloat16((unsigned short)lo);
}

// ============================================================
// mma.sync GEMM: CTA 256m x 128n x 64ch super-chunks (hi|lo 256B rows).
// 8 warps (4m x 2n), warp tile 64x64. 2-stage cp.async pipeline.
// Per ks-step: 3 products hi*hi + hi*lo + lo*hi from 16 ldm4.
// Epilogue (R11-proven): bias in store, [n][m] smem stage, BN from stage.
// ============================================================
#define STAGE_A 65536
#define STAGE_B 32768
#define STAGE_BYTES (STAGE_A + STAGE_B)
#define SMEM_DYN (2*STAGE_BYTES + 128)

template<int KH>
__device__ __forceinline__ void load_chunk(uint32_t sA, uint32_t sB,
        const __nv_bfloat16* __restrict__ A, const __nv_bfloat16* __restrict__ B,
        int n0, int c, int t) {
    int seg = t & 15, r0 = t >> 4;
    int o = seg*16;
    const char* Ab = (const char*)A + (size_t)c*256 + (size_t)seg*16;
    const char* Bb = (const char*)B + (size_t)n0*KH*2 + (size_t)c*256 + (size_t)seg*16;
    #pragma unroll
    for (int i = 0; i < 16; i++) {          // A: 256 rows
        int row = r0 + i*16;
        cp16(sA + swz256(row, o), Ab + (size_t)row*KH*2);
    }
    #pragma unroll
    for (int i = 0; i < 8; i++) {           // B: 128 rows
        int row = r0 + i*16;
        cp16(sB + swz256(row, o), Bb + (size_t)row*KH*2);
    }
    asm volatile("cp.async.commit_group;" ::: "memory");
}

template<int MODE>
__global__ void __launch_bounds__(256)
mma_gemm(const float* __restrict__ bias) {
    constexpr int SC = (MODE == 0) ? SC1 : SC2;
    constexpr int KH = SC*128;
    const __nv_bfloat16* A = (MODE == 0) ? g_W1e  : g_W2e;
    const __nv_bfloat16* B = (MODE == 0) ? g_featB : g_y2B;
    float* yT   = (MODE == 0) ? g_y1T : g_y2T;
    float* sacc = (MODE == 0) ? g_sum1 : g_sum2;
    float* qacc = (MODE == 0) ? g_sq1  : g_sq2;

    extern __shared__ char smem[];
    uint32_t sb;
    asm("{ .reg .u64 t; cvta.to.shared.u64 t, %1; cvt.u32.u64 %0, t; }"
        : "=r"(sb) : "l"(smem));
    uint32_t base = (sb + 127u) & ~127u;
    uint32_t sA0 = base,                sB0 = base + STAGE_A;
    uint32_t sA1 = base + STAGE_BYTES,  sB1 = sA1 + STAGE_A;
    float* stage = (float*)(smem + (base - sb));

    int t = threadIdx.x, wid = t >> 5, lane = t & 31;
    int wm = wid >> 1, wn = wid & 1;
    int n0 = blockIdx.x*128;
    int m0w = wm*64, n0w = wn*64;

    float acc[4][8][4];
    #pragma unroll
    for (int i = 0; i < 4; i++)
        #pragma unroll
        for (int j = 0; j < 8; j++)
            #pragma unroll
            for (int e = 0; e < 4; e++) acc[i][j][e] = 0.f;

    int laneRow = lane & 15, laneHi = lane >> 4;

    load_chunk<KH>(sA0, sB0, A, B, n0, 0, t);
    load_chunk<KH>(sA1, sB1, A, B, n0, 1, t);

    for (int c = 0; c < SC; c++) {
        if (c + 1 < SC) asm volatile("cp.async.wait_group 1;" ::: "memory");
        else            asm volatile("cp.async.wait_group 0;" ::: "memory");
        __syncthreads();
        uint32_t curA = (c & 1) ? sA1 : sA0;
        uint32_t curB = (c & 1) ? sB1 : sB0;

        #pragma unroll
        for (int ks = 0; ks < 4; ks++) {
            int o_hi = (2*ks + laneHi)*16;
            int o_lo = 128 + o_hi;
            uint32_t ah[4][4], bh[4][4], bl[4][4], al[4][4];
            #pragma unroll
            for (int mi = 0; mi < 4; mi++) {
                int row = m0w + 16*mi + laneRow;
                ldm4(ah[mi], curA + swz256(row, o_hi));
            }
            #pragma unroll
            for (int nj = 0; nj < 4; nj++) {
                int row = n0w + 16*nj + laneRow;
                ldm4(bh[nj], curB + swz256(row, o_hi));
            }
            // P1: hi * hi
            #pragma unroll
            for (int mi = 0; mi < 4; mi++)
                #pragma unroll
                for (int f = 0; f < 8; f++)
                    mma16816(acc[mi][f], ah[mi], bh[f>>1][f&1], bh[f>>1][(f&1)+2]);
            #pragma unroll
            for (int nj = 0; nj < 4; nj++) {
                int row = n0w + 16*nj + laneRow;
                ldm4(bl[nj], curB + swz256(row, o_lo));
            }
            // P2: hi * lo
            #pragma unroll
            for (int mi = 0; mi < 4; mi++)
                #pragma unroll
                for (int f = 0; f < 8; f++)
                    mma16816(acc[mi][f], ah[mi], bl[f>>1][f&1], bl[f>>1][(f&1)+2]);
            #pragma unroll
            for (int mi = 0; mi < 4; mi++) {
                int row = m0w + 16*mi + laneRow;
                ldm4(al[mi], curA + swz256(row, o_lo));
            }
            // P3: lo * hi
            #pragma unroll
            for (int mi = 0; mi < 4; mi++)
                #pragma unroll
                for (int f = 0; f < 8; f++)
                    mma16816(acc[mi][f], al[mi], bh[f>>1][f&1], bh[f>>1][(f&1)+2]);
        }
        __syncthreads();
        if (c + 2 < SC) {
            uint32_t nA = (c & 1) ? sA1 : sA0;
            uint32_t nB = (c & 1) ? sB1 : sB0;
            load_chunk<KH>(nA, nB, A, B, n0, c + 2, t);
        }
    }
    __syncthreads();   // operand smem -> stage reuse

    // ---- epilogue (R11): stage [n(128)][m(256)] fp32, pad 260 ----
    {
        int q = lane & 3, r = lane >> 2;
        #pragma unroll
        for (int mi = 0; mi < 4; mi++) {
            int m_l = m0w + 16*mi + r;
            #pragma unroll
            for (int f = 0; f < 8; f++) {
                int n_l = n0w + 8*f + 2*q;
                stage[(size_t)n_l*260 + m_l]          = acc[mi][f][0];
                stage[(size_t)(n_l+1)*260 + m_l]      = acc[mi][f][1];
                stage[(size_t)n_l*260 + m_l + 8]      = acc[mi][f][2];
                stage[(size_t)(n_l+1)*260 + m_l + 8]  = acc[mi][f][3];
            }
        }
    }
    __syncthreads();

    // contiguous store: yT[(n0+n)*256 + m], bias added
    #pragma unroll 4
    for (int idx = t; idx < 128*64; idx += 256) {
        int n_l = idx >> 6, m4 = idx & 63;
        float4 bb = __ldg((const float4*)&bias[m4*4]);
        float* sp = &stage[(size_t)n_l*260 + m4*4];
        float4 v;
        v.x = sp[0] + bb.x; v.y = sp[1] + bb.y;
        v.z = sp[2] + bb.z; v.w = sp[3] + bb.w;
        *(float4*)&yT[(size_t)(n0 + n_l)*256 + m4*4] = v;
    }

    // BN sums: thread t = channel t, reduce over 128 points
    {
        float bb = __ldg(&bias[t]);
        float s = 0.f, q2 = 0.f;
        #pragma unroll 4
        for (int j = 0; j < 128; j++) {
            float v = stage[(size_t)j*260 + t] + bb;
            s += v; q2 += v*v;
        }
        atomicAdd(&sacc[t], s);
        atomicAdd(&qacc[t], q2);
    }
}

// ============================================================
// prep2: BN1 affine in-block, relu(bn1(y1)) -> hi|lo bf16 B operand
// ============================================================
__global__ void prep2(const float* __restrict__ g, const float* __restrict__ beta) {
    __shared__ float ssc[CMID], ssh[CMID];
    int t = threadIdx.x;
    {
        float mean = g_sum1[t] * (1.0f/(float)BNT);
        float var  = g_sq1[t]  * (1.0f/(float)BNT) - mean*mean;
        float r = rsqrtf(var + 1e-5f);
        float sc = g[t]*r;
        ssc[t] = sc;
        ssh[t] = beta[t] - mean*sc;
    }
    __syncthreads();
    int gi = blockIdx.x*256 + t;
    int n = gi >> 5, kg = gi & 31, k0 = kg*8;
    float v[8];
    #pragma unroll
    for (int h = 0; h < 2; h++) {
        float4 y = *(const float4*)&g_y1T[(size_t)n*CMID + k0 + h*4];
        int kb = k0 + h*4;
        v[h*4+0] = fmaxf(y.x*ssc[kb+0] + ssh[kb+0], 0.f);
        v[h*4+1] = fmaxf(y.y*ssc[kb+1] + ssh[kb+1], 0.f);
        v[h*4+2] = fmaxf(y.z*ssc[kb+2] + ssh[kb+2], 0.f);
        v[h*4+3] = fmaxf(y.w*ssc[kb+3] + ssh[kb+3], 0.f);
    }
    char* base = (char*)g_y2B + (size_t)n*KH2*2 + (size_t)(k0>>6)*256 + (size_t)(k0&63)*2;
    store_packHL8(base, base + 128, v);
}

// ============================================================
// final: BN2 affine in-block, y2T [n][m] -> out [b][m][n] + ReLU
// ============================================================
__global__ void final_out(float* __restrict__ out,
                          const float* __restrict__ g, const float* __restrict__ beta) {
    __shared__ float tile[32][33];
    __shared__ float ssc[32], ssh[32];
    int b = blockIdx.z, m0 = blockIdx.y*32, n0 = blockIdx.x*32;
    int lx = threadIdx.x, ly = threadIdx.y;
    if (ly == 0) {
        int m = m0 + lx;
        float mean = g_sum2[m] * (1.0f/(float)BNT);
        float var  = g_sq2[m]  * (1.0f/(float)BNT) - mean*mean;
        float r = rsqrtf(var + 1e-5f);
        float sc = g[m]*r;
        ssc[lx] = sc;
        ssh[lx] = beta[m] - mean*sc;
    }
    #pragma unroll
    for (int i = ly; i < 32; i += 8)
        tile[i][lx] = g_y2T[(size_t)(b*NPTS + n0 + i)*COUT + m0 + lx];
    __syncthreads();
    #pragma unroll
    for (int i = ly; i < 32; i += 8) {
        float v = tile[lx][i]*ssc[i] + ssh[i];
        out[((size_t)b*COUT + m0 + i)*NPTS + n0 + lx] = fmaxf(v, 0.f);
    }
}

// ============================================================
extern "C" void kernel_launch(void* const* d_in, const int* in_sizes, int n_in,
                              void* d_out, int out_size) {
    const float* pos1 = (const float*)d_in[0];
    const float* pos2 = (const float*)d_in[1];
    const float* f1   = (const float*)d_in[2];
    const float* f2   = (const float*)d_in[3];
    const float* W1   = (const float*)d_in[4];
    const float* b1   = (const float*)d_in[5];
    const float* g1   = (const float*)d_in[6];
    const float* be1  = (const float*)d_in[7];
    const float* W2   = (const float*)d_in[8];
    const float* b2   = (const float*)d_in[9];
    const float* g2   = (const float*)d_in[10];
    const float* be2  = (const float*)d_in[11];
    float* out = (float*)d_out;

    cudaFuncSetAttribute(mma_gemm<0>, cudaFuncAttributeMaxDynamicSharedMemorySize, SMEM_DYN);
    cudaFuncSetAttribute(mma_gemm<1>, cudaFuncAttributeMaxDynamicSharedMemorySize, SMEM_DYN);

    knn_kernel   <<<dim3(NPTS/256, BB), 256>>>(pos1, pos2);
    transpose_f2 <<<dim3(SPTS/32, D2C/32, BB), dim3(32,8)>>>(f2);
    interp_kernel<<<BNT/8, 256>>>();
    copy_f1      <<<dim3(NPTS/32, D1C/64, BB), 256>>>(f1);
    wexpand_all  <<<(CMID*CIN + COUT*CMID)/256, 256>>>(W1, W2);

    mma_gemm<0>  <<<BNT/128, 256, SMEM_DYN>>>(b1);
    prep2        <<<(BNT*32)/256, 256>>>(g1, be1);
    mma_gemm<1>  <<<BNT/128, 256, SMEM_DYN>>>(b2);
    final_out    <<<dim3(NPTS/32, COUT/32, BB), dim3(32,8)>>>(out, g2, be2);
}

// round 15
// speedup vs baseline: 1.0674x; 1.0106x over previous
#include <cuda_runtime.h>
#include <cuda_bf16.h>
#include <math.h>
#include <stdint.h>

#define BB    4
#define NPTS  8192
#define SPTS  2048
#define D1C   128
#define D2C   256
#define CIN   384
#define CMID  256
#define COUT  256
#define BNT   (BB*NPTS)     // 32768
#define KH1   (2*CIN)       // 768 bf16 per point (hi|lo blocks of 64)
#define KH2   (2*CMID)      // 512
#define SC1   (CIN/64)      // 6 super-chunks
#define SC2   (CMID/64)     // 4

// ---------------- scratch (device globals) ----------------
__device__ __align__(256) float          g_f2t[BB*SPTS*D2C];          // [B,S,D2]
__device__ __align__(256) __nv_bfloat16  g_featB[(size_t)BNT*KH1];    // B op GEMM1 (hi|lo)
__device__ __align__(256) __nv_bfloat16  g_W1e[CMID*KH1];             // A op GEMM1 (hi|lo)
__device__ __align__(256) __nv_bfloat16  g_W2e[COUT*KH2];             // A op GEMM2 (hi|lo)
__device__ __align__(256) float          g_y1T[(size_t)BNT*CMID];     // y1 pre-BN, point-major
__device__ __align__(256) __nv_bfloat16  g_y2B[(size_t)BNT*KH2];      // B op GEMM2 (hi|lo)
__device__ __align__(256) float          g_y2T[(size_t)BNT*COUT];     // y2 pre-BN, point-major
__device__ int   g_idx[BNT*3];
__device__ float g_w[BNT*3];
__device__ float g_sum1[CMID], g_sq1[CMID], g_sum2[COUT], g_sq2[COUT];

// ---------------- small helpers ----------------
__device__ __forceinline__ void cp16(uint32_t dst, const void* src){
    asm volatile("cp.async.cg.shared.global [%0], [%1], 16;" :: "r"(dst), "l"(src));
}
__device__ __forceinline__ void ldm4(uint32_t* r, uint32_t addr){
    asm volatile("ldmatrix.sync.aligned.m8n8.x4.shared.b16 {%0,%1,%2,%3}, [%4];"
        : "=r"(r[0]), "=r"(r[1]), "=r"(r[2]), "=r"(r[3]) : "r"(addr));
}
__device__ __forceinline__ void mma16816(float* d, const uint32_t* a, uint32_t b0, uint32_t b1){
    asm volatile(
        "mma.sync.aligned.m16n8k16.row.col.f32.bf16.bf16.f32 "
        "{%0,%1,%2,%3}, {%4,%5,%6,%7}, {%8,%9}, {%0,%1,%2,%3};"
        : "+f"(d[0]), "+f"(d[1]), "+f"(d[2]), "+f"(d[3])
        : "r"(a[0]), "r"(a[1]), "r"(a[2]), "r"(a[3]), "r"(b0), "r"(b1));
}

__device__ __forceinline__ void split_bf(float v, uint32_t& hi, uint32_t& lo){
    __nv_bfloat16 h = __float2bfloat16(v);
    float r = v - __bfloat162float(h);
    __nv_bfloat16 l = __float2bfloat16(r);
    hi = (uint32_t)__bfloat16_as_ushort(h);
    lo = (uint32_t)__bfloat16_as_ushort(l);
}

// 8 consecutive channels -> hi uint4 + lo uint4 (16B each, aligned)
__device__ __forceinline__ void store_packHL8(void* dhi, void* dlo, const float* v){
    uint32_t h[8], l[8];
    #pragma unroll
    for (int j = 0; j < 8; j++) split_bf(v[j], h[j], l[j]);
    *(uint4*)dhi = make_uint4(h[0]|(h[1]<<16), h[2]|(h[3]<<16), h[4]|(h[5]<<16), h[6]|(h[7]<<16));
    *(uint4*)dlo = make_uint4(l[0]|(l[1]<<16), l[2]|(l[3]<<16), l[4]|(l[5]<<16), l[6]|(l[7]<<16));
}

// smem addr within a 256B-row tile, SW within each 128B half
__device__ __forceinline__ uint32_t swz256(int row, int o){
    return (uint32_t)(row*256 + (o & 128) + ((o & 127) ^ ((row & 7)*16)));
}

#define KNN_INS(dv,iv,d0,i0,d1,i1,d2,i2)                          \
    if ((dv) < (d2)) {                                            \
        if ((dv) < (d1)) {                                        \
            d2 = d1; i2 = i1;                                     \
            if ((dv) < (d0)) { d1 = d0; i1 = i0; d0 = dv; i0 = iv; } \
            else             { d1 = dv; i1 = iv; }                \
        } else { d2 = dv; i2 = iv; }                              \
    }

// ============================================================
// prep_all: fused knn + transpose_f2 + copy_f1 + wexpand
// flat block dispatch; 256 threads; 32KB dynamic smem union
//   [0, 128)       knn       (b = blk>>5, 256 pts/block)
//   [128, 2176)    transpose_f2
//   [2176, 4224)   copy_f1
//   [4224, 4864)   wexpand
// ============================================================
__global__ void prep_all(const float* __restrict__ pos1,
                         const float* __restrict__ pos2,
                         const float* __restrict__ f2,
                         const float* __restrict__ f1,
                         const float* __restrict__ W1,
                         const float* __restrict__ W2) {
    extern __shared__ char dsm[];
    int blk = blockIdx.x;
    int t = threadIdx.x;

    if (blk < 128) {
        // ---------------- knn (4 candidate streams) ----------------
        float4* sp = (float4*)dsm;
        int b = blk >> 5;
        if (blk == 0) {
            g_sum1[t] = 0.f; g_sq1[t] = 0.f; g_sum2[t] = 0.f; g_sq2[t] = 0.f;
        }
        const float* p2 = pos2 + (size_t)b*3*SPTS;
        for (int s = t; s < SPTS; s += 256) {
            float x = p2[s], y = p2[SPTS+s], z = p2[2*SPTS+s];
            sp[s] = make_float4(x, y, z, x*x+y*y+z*z);
        }
        __syncthreads();

        int n = (blk & 31)*256 + t;
        const float* p1 = pos1 + (size_t)b*3*NPTS;
        float px = p1[n], py = p1[NPTS+n], pz = p1[2*NPTS+n];
        float n1 = px*px+py*py+pz*pz;

        float d0a=1e30f,d1a=1e30f,d2a=1e30f; int i0a=0,i1a=0,i2a=0;
        float d0b=1e30f,d1b=1e30f,d2b=1e30f; int i0b=512,i1b=512,i2b=512;
        float d0c=1e30f,d1c=1e30f,d2c=1e30f; int i0c=1024,i1c=1024,i2c=1024;
        float d0d=1e30f,d1d=1e30f,d2d=1e30f; int i0d=1536,i1d=1536,i2d=1536;
        #pragma unroll 2
        for (int s = 0; s < 512; s++) {
            float4 ca = sp[s];
            float da = n1 - 2.0f*(px*ca.x + py*ca.y + pz*ca.z) + ca.w;
            float4 cb = sp[s + 512];
            float db = n1 - 2.0f*(px*cb.x + py*cb.y + pz*cb.z) + cb.w;
            float4 cc = sp[s + 1024];
            float dc = n1 - 2.0f*(px*cc.x + py*cc.y + pz*cc.z) + cc.w;
            float4 cd = sp[s + 1536];
            float dd = n1 - 2.0f*(px*cd.x + py*cd.y + pz*cd.z) + cd.w;
            KNN_INS(da, s,        d0a,i0a, d1a,i1a, d2a,i2a);
            KNN_INS(db, s + 512,  d0b,i0b, d1b,i1b, d2b,i2b);
            KNN_INS(dc, s + 1024, d0c,i0c, d1c,i1c, d2c,i2c);
            KNN_INS(dd, s + 1536, d0d,i0d, d1d,i1d, d2d,i2d);
        }
        // merge in increasing index-range order; strict < keeps low-index on tie
        KNN_INS(d0b, i0b, d0a,i0a, d1a,i1a, d2a,i2a);
        KNN_INS(d1b, i1b, d0a,i0a, d1a,i1a, d2a,i2a);
        KNN_INS(d2b, i2b, d0a,i0a, d1a,i1a, d2a,i2a);
        KNN_INS(d0c, i0c, d0a,i0a, d1a,i1a, d2a,i2a);
        KNN_INS(d1c, i1c, d0a,i0a, d1a,i1a, d2a,i2a);
        KNN_INS(d2c, i2c, d0a,i0a, d1a,i1a, d2a,i2a);
        KNN_INS(d0d, i0d, d0a,i0a, d1a,i1a, d2a,i2a);
        KNN_INS(d1d, i1d, d0a,i0a, d1a,i1a, d2a,i2a);
        KNN_INS(d2d, i2d, d0a,i0a, d1a,i1a, d2a,i2a);

        float a0 = fmaxf(d0a, 1e-10f), a1 = fmaxf(d1a, 1e-10f), a2 = fmaxf(d2a, 1e-10f);
        float w0 = 1.0f/a0, w1 = 1.0f/a1, w2 = 1.0f/a2;
        float inv = 1.0f/(w0+w1+w2);
        int base = (b*NPTS + n)*3;
        g_idx[base+0]=i0a; g_idx[base+1]=i1a; g_idx[base+2]=i2a;
        g_w[base+0]=w0*inv; g_w[base+1]=w1*inv; g_w[base+2]=w2*inv;

    } else if (blk < 2176) {
        // ---------------- transpose_f2 ----------------
        float (*tt)[33] = (float(*)[33])dsm;
        int idx = blk - 128;
        int s0 = (idx & 63)*32, d0 = ((idx >> 6) & 7)*32, b = idx >> 9;
        int lx = t & 31, ly = t >> 5;
        const float* src = f2 + (size_t)b*D2C*SPTS;
        #pragma unroll
        for (int i = ly; i < 32; i += 8)
            tt[i][lx] = src[(size_t)(d0+i)*SPTS + s0 + lx];
        __syncthreads();
        float* dst = g_f2t + (size_t)b*SPTS*D2C;
        #pragma unroll
        for (int i = ly; i < 32; i += 8)
            dst[(size_t)(s0+i)*D2C + d0 + lx] = tt[lx][i];

    } else if (blk < 4224) {
        // ---------------- copy_f1 -> featB channels [D2, CIN) ----------------
        float (*tile)[33] = (float(*)[33])dsm;
        int idx = blk - 2176;
        int n0 = (idx & 255)*32, d0 = ((idx >> 8) & 1)*64, b = idx >> 9;
        int lx = t & 31, ly = t >> 5;
        const float* src = f1 + ((size_t)b*D1C + d0)*NPTS + n0;
        #pragma unroll
        for (int i = ly; i < 64; i += 8)
            tile[i][lx] = src[(size_t)i*NPTS + lx];
        __syncthreads();
        int g = t & 7, nn = t >> 3;
        int n = b*NPTS + n0 + nn;
        int c = D2C + d0 + g*8;
        float v[8];
        #pragma unroll
        for (int j = 0; j < 8; j++) v[j] = tile[g*8+j][nn];
        char* base = (char*)g_featB + (size_t)n*KH1*2 + (size_t)(c>>6)*256 + (size_t)(c&63)*2;
        store_packHL8(base, base + 128, v);

    } else {
        // ---------------- wexpand (both layers) ----------------
        int i = (blk - 4224)*256 + t;
        float v; __nv_bfloat16* p;
        if (i < CMID*CIN) {
            int m = i / CIN, k = i - m*CIN;
            v = W1[i];
            p = g_W1e + (size_t)m*KH1 + (k>>6)*128 + (k&63);
        } else {
            int j = i - CMID*CIN;
            int m = j / CMID, k = j - m*CMID;
            v = W2[j];
            p = g_W2e + (size_t)m*KH2 + (k>>6)*128 + (k&63);
        }
        uint32_t hi, lo; split_bf(v, hi, lo);
        p[0]  = __ushort_as_bfloat16((unsigned short)hi);
        p[64] = __ushort_as_bfloat16((unsigned short)lo);
    }
}

// ============================================================
// interp: weighted 3-NN -> g_featB channels [0, D2) as hi|lo blocks
// ============================================================
__global__ void interp_kernel() {
    int t = threadIdx.x;
    int p = blockIdx.x*8 + (t >> 5);
    int kg = t & 31;
    int i0 = __ldg(&g_idx[p*3+0]), i1 = __ldg(&g_idx[p*3+1]), i2 = __ldg(&g_idx[p*3+2]);
    float w0 = __ldg(&g_w[p*3+0]), w1 = __ldg(&g_w[p*3+1]), w2 = __ldg(&g_w[p*3+2]);
    int b = p >> 13;
    const float* f2 = g_f2t + (size_t)b*SPTS*D2C;
    int k0 = kg*8;
    float v[8];
    #pragma unroll
    for (int h = 0; h < 2; h++) {
        float4 a = *(const float4*)&f2[(size_t)i0*D2C + k0 + h*4];
        float4 c = *(const float4*)&f2[(size_t)i1*D2C + k0 + h*4];
        float4 d = *(const float4*)&f2[(size_t)i2*D2C + k0 + h*4];
        v[h*4+0] = w0*a.x + w1*c.x + w2*d.x;
        v[h*4+1] = w0*a.y + w1*c.y + w2*d.y;
        v[h*4+2] = w0*a.z + w1*c.z + w2*d.z;
        v[h*4+3] = w0*a.w + w1*c.w + w2*d.w;
    }
    char* base = (char*)g_featB + (size_t)p*KH1*2 + (size_t)(k0>>6)*256 + (size_t)(k0&63)*2;
    store_packHL8(base, base + 128, v);
}

// ============================================================
// mma.sync GEMM (unchanged from R13): CTA 256m x 128n, hi|lo 3-product
// ============================================================
#define STAGE_A 65536
#define STAGE_B 32768
#define STAGE_BYTES (STAGE_A + STAGE_B)
#define SMEM_DYN (2*STAGE_BYTES + 128)

template<int KH>
__device__ __forceinline__ void load_chunk(uint32_t sA, uint32_t sB,
        const __nv_bfloat16* __restrict__ A, const __nv_bfloat16* __restrict__ B,
        int n0, int c, int t) {
    int seg = t & 15, r0 = t >> 4;
    int o = seg*16;
    const char* Ab = (const char*)A + (size_t)c*256 + (size_t)seg*16;
    const char* Bb = (const char*)B + (size_t)n0*KH*2 + (size_t)c*256 + (size_t)seg*16;
    #pragma unroll
    for (int i = 0; i < 16; i++) {
        int row = r0 + i*16;
        cp16(sA + swz256(row, o), Ab + (size_t)row*KH*2);
    }
    #pragma unroll
    for (int i = 0; i < 8; i++) {
        int row = r0 + i*16;
        cp16(sB + swz256(row, o), Bb + (size_t)row*KH*2);
    }
    asm volatile("cp.async.commit_group;" ::: "memory");
}

template<int MODE>
__global__ void __launch_bounds__(256)
mma_gemm(const float* __restrict__ bias) {
    constexpr int SC = (MODE == 0) ? SC1 : SC2;
    constexpr int KH = SC*128;
    const __nv_bfloat16* A = (MODE == 0) ? g_W1e  : g_W2e;
    const __nv_bfloat16* B = (MODE == 0) ? g_featB : g_y2B;
    float* yT   = (MODE == 0) ? g_y1T : g_y2T;
    float* sacc = (MODE == 0) ? g_sum1 : g_sum2;
    float* qacc = (MODE == 0) ? g_sq1  : g_sq2;

    extern __shared__ char smem[];
    uint32_t sb;
    asm("{ .reg .u64 t; cvta.to.shared.u64 t, %1; cvt.u32.u64 %0, t; }"
        : "=r"(sb) : "l"(smem));
    uint32_t base = (sb + 127u) & ~127u;
    uint32_t sA0 = base,                sB0 = base + STAGE_A;
    uint32_t sA1 = base + STAGE_BYTES,  sB1 = sA1 + STAGE_A;
    float* stage = (float*)(smem + (base - sb));

    int t = threadIdx.x, wid = t >> 5, lane = t & 31;
    int wm = wid >> 1, wn = wid & 1;
    int n0 = blockIdx.x*128;
    int m0w = wm*64, n0w = wn*64;

    float acc[4][8][4];
    #pragma unroll
    for (int i = 0; i < 4; i++)
        #pragma unroll
        for (int j = 0; j < 8; j++)
            #pragma unroll
            for (int e = 0; e < 4; e++) acc[i][j][e] = 0.f;

    int laneRow = lane & 15, laneHi = lane >> 4;

    load_chunk<KH>(sA0, sB0, A, B, n0, 0, t);
    load_chunk<KH>(sA1, sB1, A, B, n0, 1, t);

    for (int c = 0; c < SC; c++) {
        if (c + 1 < SC) asm volatile("cp.async.wait_group 1;" ::: "memory");
        else            asm volatile("cp.async.wait_group 0;" ::: "memory");
        __syncthreads();
        uint32_t curA = (c & 1) ? sA1 : sA0;
        uint32_t curB = (c & 1) ? sB1 : sB0;

        #pragma unroll
        for (int ks = 0; ks < 4; ks++) {
            int o_hi = (2*ks + laneHi)*16;
            int o_lo = 128 + o_hi;
            uint32_t ah[4][4], bh[4][4], bl[4][4], al[4][4];
            #pragma unroll
            for (int mi = 0; mi < 4; mi++) {
                int row = m0w + 16*mi + laneRow;
                ldm4(ah[mi], curA + swz256(row, o_hi));
            }
            #pragma unroll
            for (int nj = 0; nj < 4; nj++) {
                int row = n0w + 16*nj + laneRow;
                ldm4(bh[nj], curB + swz256(row, o_hi));
            }
            #pragma unroll
            for (int mi = 0; mi < 4; mi++)
                #pragma unroll
                for (int f = 0; f < 8; f++)
                    mma16816(acc[mi][f], ah[mi], bh[f>>1][f&1], bh[f>>1][(f&1)+2]);
            #pragma unroll
            for (int nj = 0; nj < 4; nj++) {
                int row = n0w + 16*nj + laneRow;
                ldm4(bl[nj], curB + swz256(row, o_lo));
            }
            #pragma unroll
            for (int mi = 0; mi < 4; mi++)
                #pragma unroll
                for (int f = 0; f < 8; f++)
                    mma16816(acc[mi][f], ah[mi], bl[f>>1][f&1], bl[f>>1][(f&1)+2]);
            #pragma unroll
            for (int mi = 0; mi < 4; mi++) {
                int row = m0w + 16*mi + laneRow;
                ldm4(al[mi], curA + swz256(row, o_lo));
            }
            #pragma unroll
            for (int mi = 0; mi < 4; mi++)
                #pragma unroll
                for (int f = 0; f < 8; f++)
                    mma16816(acc[mi][f], al[mi], bh[f>>1][f&1], bh[f>>1][(f&1)+2]);
        }
        __syncthreads();
        if (c + 2 < SC) {
            uint32_t nA = (c & 1) ? sA1 : sA0;
            uint32_t nB = (c & 1) ? sB1 : sB0;
            load_chunk<KH>(nA, nB, A, B, n0, c + 2, t);
        }
    }
    __syncthreads();

    // ---- epilogue: stage [n(128)][m(256)] fp32, pad 260 ----
    {
        int q = lane & 3, r = lane >> 2;
        #pragma unroll
        for (int mi = 0; mi < 4; mi++) {
            int m_l = m0w + 16*mi + r;
            #pragma unroll
            for (int f = 0; f < 8; f++) {
                int n_l = n0w + 8*f + 2*q;
                stage[(size_t)n_l*260 + m_l]          = acc[mi][f][0];
                stage[(size_t)(n_l+1)*260 + m_l]      = acc[mi][f][1];
                stage[(size_t)n_l*260 + m_l + 8]      = acc[mi][f][2];
                stage[(size_t)(n_l+1)*260 + m_l + 8]  = acc[mi][f][3];
            }
        }
    }
    __syncthreads();

    #pragma unroll 4
    for (int idx = t; idx < 128*64; idx += 256) {
        int n_l = idx >> 6, m4 = idx & 63;
        float4 bb = __ldg((const float4*)&bias[m4*4]);
        float* sp = &stage[(size_t)n_l*260 + m4*4];
        float4 v;
        v.x = sp[0] + bb.x; v.y = sp[1] + bb.y;
        v.z = sp[2] + bb.z; v.w = sp[3] + bb.w;
        *(float4*)&yT[(size_t)(n0 + n_l)*256 + m4*4] = v;
    }

    {
        float bb = __ldg(&bias[t]);
        float s = 0.f, q2 = 0.f;
        #pragma unroll 4
        for (int j = 0; j < 128; j++) {
            float v = stage[(size_t)j*260 + t] + bb;
            s += v; q2 += v*v;
        }
        atomicAdd(&sacc[t], s);
        atomicAdd(&qacc[t], q2);
    }
}

// ============================================================
// prep2: BN1 affine in-block, relu(bn1(y1)) -> hi|lo bf16 B operand
// ============================================================
__global__ void prep2(const float* __restrict__ g, const float* __restrict__ beta) {
    __shared__ float ssc[CMID], ssh[CMID];
    int t = threadIdx.x;
    {
        float mean = g_sum1[t] * (1.0f/(float)BNT);
        float var  = g_sq1[t]  * (1.0f/(float)BNT) - mean*mean;
        float r = rsqrtf(var + 1e-5f);
        float sc = g[t]*r;
        ssc[t] = sc;
        ssh[t] = beta[t] - mean*sc;
    }
    __syncthreads();
    int gi = blockIdx.x*256 + t;
    int n = gi >> 5, kg = gi & 31, k0 = kg*8;
    float v[8];
    #pragma unroll
    for (int h = 0; h < 2; h++) {
        float4 y = *(const float4*)&g_y1T[(size_t)n*CMID + k0 + h*4];
        int kb = k0 + h*4;
        v[h*4+0] = fmaxf(y.x*ssc[kb+0] + ssh[kb+0], 0.f);
        v[h*4+1] = fmaxf(y.y*ssc[kb+1] + ssh[kb+1], 0.f);
        v[h*4+2] = fmaxf(y.z*ssc[kb+2] + ssh[kb+2], 0.f);
        v[h*4+3] = fmaxf(y.w*ssc[kb+3] + ssh[kb+3], 0.f);
    }
    char* base = (char*)g_y2B + (size_t)n*KH2*2 + (size_t)(k0>>6)*256 + (size_t)(k0&63)*2;
    store_packHL8(base, base + 128, v);
}

// ============================================================
// final: BN2 affine in-block, y2T [n][m] -> out [b][m][n] + ReLU
// ============================================================
__global__ void final_out(float* __restrict__ out,
                          const float* __restrict__ g, const float* __restrict__ beta) {
    __shared__ float tile[32][33];
    __shared__ float ssc[32], ssh[32];
    int b = blockIdx.z, m0 = blockIdx.y*32, n0 = blockIdx.x*32;
    int lx = threadIdx.x, ly = threadIdx.y;
    if (ly == 0) {
        int m = m0 + lx;
        float mean = g_sum2[m] * (1.0f/(float)BNT);
        float var  = g_sq2[m]  * (1.0f/(float)BNT) - mean*mean;
        float r = rsqrtf(var + 1e-5f);
        float sc = g[m]*r;
        ssc[lx] = sc;
        ssh[lx] = beta[m] - mean*sc;
    }
    #pragma unroll
    for (int i = ly; i < 32; i += 8)
        tile[i][lx] = g_y2T[(size_t)(b*NPTS + n0 + i)*COUT + m0 + lx];
    __syncthreads();
    #pragma unroll
    for (int i = ly; i < 32; i += 8) {
        float v = tile[lx][i]*ssc[i] + ssh[i];
        out[((size_t)b*COUT + m0 + i)*NPTS + n0 + lx] = fmaxf(v, 0.f);
    }
}

// ============================================================
extern "C" void kernel_launch(void* const* d_in, const int* in_sizes, int n_in,
                              void* d_out, int out_size) {
    const float* pos1 = (const float*)d_in[0];
    const float* pos2 = (const float*)d_in[1];
    const float* f1   = (const float*)d_in[2];
    const float* f2   = (const float*)d_in[3];
    const float* W1   = (const float*)d_in[4];
    const float* b1   = (const float*)d_in[5];
    const float* g1   = (const float*)d_in[6];
    const float* be1  = (const float*)d_in[7];
    const float* W2   = (const float*)d_in[8];
    const float* b2   = (const float*)d_in[9];
    const float* g2   = (const float*)d_in[10];
    const float* be2  = (const float*)d_in[11];
    float* out = (float*)d_out;

    cudaFuncSetAttribute(mma_gemm<0>, cudaFuncAttributeMaxDynamicSharedMemorySize, SMEM_DYN);
    cudaFuncSetAttribute(mma_gemm<1>, cudaFuncAttributeMaxDynamicSharedMemorySize, SMEM_DYN);

    prep_all     <<<4864, 256, 32768>>>(pos1, pos2, f2, f1, W1, W2);
    interp_kernel<<<BNT/8, 256>>>();

    mma_gemm<0>  <<<BNT/128, 256, SMEM_DYN>>>(b1);
    prep2        <<<(BNT*32)/256, 256>>>(g1, be1);
    mma_gemm<1>  <<<BNT/128, 256, SMEM_DYN>>>(b2);
    final_out    <<<dim3(NPTS/32, COUT/32, BB), dim3(32,8)>>>(out, g2, be2);
}

// round 16
// speedup vs baseline: 1.0828x; 1.0144x over previous
#include <cuda_runtime.h>
#include <cuda_bf16.h>
#include <math.h>
#include <stdint.h>

#define BB    4
#define NPTS  8192
#define SPTS  2048
#define D1C   128
#define D2C   256
#define CIN   384
#define CMID  256
#define COUT  256
#define BNT   (BB*NPTS)     // 32768
#define KH1   (2*CIN)       // 768 bf16 per point (hi|lo blocks of 64)
#define KH2   (2*CMID)      // 512
#define SC1   (CIN/64)      // 6 super-chunks
#define SC2   (CMID/64)     // 4

// ---------------- scratch (device globals) ----------------
__device__ __align__(256) float          g_f2t[BB*SPTS*D2C];          // [B,S,D2]
__device__ __align__(256) __nv_bfloat16  g_featB[(size_t)BNT*KH1];    // B op GEMM1 (hi|lo)
__device__ __align__(256) __nv_bfloat16  g_W1e[CMID*KH1];             // A op GEMM1 (hi|lo)
__device__ __align__(256) __nv_bfloat16  g_W2e[COUT*KH2];             // A op GEMM2 (hi|lo)
__device__ __align__(256) float          g_y1T[(size_t)BNT*CMID];     // y1 pre-BN, point-major
__device__ __align__(256) __nv_bfloat16  g_y2B[(size_t)BNT*KH2];      // B op GEMM2 (hi|lo)
__device__ __align__(256) float          g_y2T[(size_t)BNT*COUT];     // y2 pre-BN, point-major
__device__ int   g_idx[BNT*3];
__device__ float g_w[BNT*3];
__device__ float g_sum1[CMID], g_sq1[CMID], g_sum2[COUT], g_sq2[COUT];

// ---------------- small helpers ----------------
__device__ __forceinline__ void cp16(uint32_t dst, const void* src){
    asm volatile("cp.async.cg.shared.global [%0], [%1], 16;" :: "r"(dst), "l"(src));
}
__device__ __forceinline__ void ldm4(uint32_t* r, uint32_t addr){
    asm volatile("ldmatrix.sync.aligned.m8n8.x4.shared.b16 {%0,%1,%2,%3}, [%4];"
        : "=r"(r[0]), "=r"(r[1]), "=r"(r[2]), "=r"(r[3]) : "r"(addr));
}
__device__ __forceinline__ void mma16816(float* d, const uint32_t* a, uint32_t b0, uint32_t b1){
    asm volatile(
        "mma.sync.aligned.m16n8k16.row.col.f32.bf16.bf16.f32 "
        "{%0,%1,%2,%3}, {%4,%5,%6,%7}, {%8,%9}, {%0,%1,%2,%3};"
        : "+f"(d[0]), "+f"(d[1]), "+f"(d[2]), "+f"(d[3])
        : "r"(a[0]), "r"(a[1]), "r"(a[2]), "r"(a[3]), "r"(b0), "r"(b1));
}

__device__ __forceinline__ void split_bf(float v, uint32_t& hi, uint32_t& lo){
    __nv_bfloat16 h = __float2bfloat16(v);
    float r = v - __bfloat162float(h);
    __nv_bfloat16 l = __float2bfloat16(r);
    hi = (uint32_t)__bfloat16_as_ushort(h);
    lo = (uint32_t)__bfloat16_as_ushort(l);
}

// 8 consecutive channels -> hi uint4 + lo uint4 (16B each, aligned)
__device__ __forceinline__ void store_packHL8(void* dhi, void* dlo, const float* v){
    uint32_t h[8], l[8];
    #pragma unroll
    for (int j = 0; j < 8; j++) split_bf(v[j], h[j], l[j]);
    *(uint4*)dhi = make_uint4(h[0]|(h[1]<<16), h[2]|(h[3]<<16), h[4]|(h[5]<<16), h[6]|(h[7]<<16));
    *(uint4*)dlo = make_uint4(l[0]|(l[1]<<16), l[2]|(l[3]<<16), l[4]|(l[5]<<16), l[6]|(l[7]<<16));
}

// smem addr within a 256B-row tile, SW within each 128B half
__device__ __forceinline__ uint32_t swz256(int row, int o){
    return (uint32_t)(row*256 + (o & 128) + ((o & 127) ^ ((row & 7)*16)));
}

#define KNN_INS(dv,iv,d0,i0,d1,i1,d2,i2)                          \
    if ((dv) < (d2)) {                                            \
        if ((dv) < (d1)) {                                        \
            d2 = d1; i2 = i1;                                     \
            if ((dv) < (d0)) { d1 = d0; i1 = i0; d0 = dv; i0 = iv; } \
            else             { d1 = dv; i1 = iv; }                \
        } else { d2 = dv; i2 = iv; }                              \
    }

// ============================================================
// prep_all: fused knn + transpose_f2 + copy_f1 + wexpand
// ============================================================
__global__ void prep_all(const float* __restrict__ pos1,
                         const float* __restrict__ pos2,
                         const float* __restrict__ f2,
                         const float* __restrict__ f1,
                         const float* __restrict__ W1,
                         const float* __restrict__ W2) {
    extern __shared__ char dsm[];
    int blk = blockIdx.x;
    int t = threadIdx.x;

    if (blk < 128) {
        // ---------------- knn (4 candidate streams) ----------------
        float4* sp = (float4*)dsm;
        int b = blk >> 5;
        if (blk == 0) {
            g_sum1[t] = 0.f; g_sq1[t] = 0.f; g_sum2[t] = 0.f; g_sq2[t] = 0.f;
        }
        const float* p2 = pos2 + (size_t)b*3*SPTS;
        for (int s = t; s < SPTS; s += 256) {
            float x = p2[s], y = p2[SPTS+s], z = p2[2*SPTS+s];
            sp[s] = make_float4(x, y, z, x*x+y*y+z*z);
        }
        __syncthreads();

        int n = (blk & 31)*256 + t;
        const float* p1 = pos1 + (size_t)b*3*NPTS;
        float px = p1[n], py = p1[NPTS+n], pz = p1[2*NPTS+n];
        float n1 = px*px+py*py+pz*pz;

        float d0a=1e30f,d1a=1e30f,d2a=1e30f; int i0a=0,i1a=0,i2a=0;
        float d0b=1e30f,d1b=1e30f,d2b=1e30f; int i0b=512,i1b=512,i2b=512;
        float d0c=1e30f,d1c=1e30f,d2c=1e30f; int i0c=1024,i1c=1024,i2c=1024;
        float d0d=1e30f,d1d=1e30f,d2d=1e30f; int i0d=1536,i1d=1536,i2d=1536;
        #pragma unroll 2
        for (int s = 0; s < 512; s++) {
            float4 ca = sp[s];
            float da = n1 - 2.0f*(px*ca.x + py*ca.y + pz*ca.z) + ca.w;
            float4 cb = sp[s + 512];
            float db = n1 - 2.0f*(px*cb.x + py*cb.y + pz*cb.z) + cb.w;
            float4 cc = sp[s + 1024];
            float dc = n1 - 2.0f*(px*cc.x + py*cc.y + pz*cc.z) + cc.w;
            float4 cd = sp[s + 1536];
            float dd = n1 - 2.0f*(px*cd.x + py*cd.y + pz*cd.z) + cd.w;
            KNN_INS(da, s,        d0a,i0a, d1a,i1a, d2a,i2a);
            KNN_INS(db, s + 512,  d0b,i0b, d1b,i1b, d2b,i2b);
            KNN_INS(dc, s + 1024, d0c,i0c, d1c,i1c, d2c,i2c);
            KNN_INS(dd, s + 1536, d0d,i0d, d1d,i1d, d2d,i2d);
        }
        KNN_INS(d0b, i0b, d0a,i0a, d1a,i1a, d2a,i2a);
        KNN_INS(d1b, i1b, d0a,i0a, d1a,i1a, d2a,i2a);
        KNN_INS(d2b, i2b, d0a,i0a, d1a,i1a, d2a,i2a);
        KNN_INS(d0c, i0c, d0a,i0a, d1a,i1a, d2a,i2a);
        KNN_INS(d1c, i1c, d0a,i0a, d1a,i1a, d2a,i2a);
        KNN_INS(d2c, i2c, d0a,i0a, d1a,i1a, d2a,i2a);
        KNN_INS(d0d, i0d, d0a,i0a, d1a,i1a, d2a,i2a);
        KNN_INS(d1d, i1d, d0a,i0a, d1a,i1a, d2a,i2a);
        KNN_INS(d2d, i2d, d0a,i0a, d1a,i1a, d2a,i2a);

        float a0 = fmaxf(d0a, 1e-10f), a1 = fmaxf(d1a, 1e-10f), a2 = fmaxf(d2a, 1e-10f);
        float w0 = 1.0f/a0, w1 = 1.0f/a1, w2 = 1.0f/a2;
        float inv = 1.0f/(w0+w1+w2);
        int base = (b*NPTS + n)*3;
        g_idx[base+0]=i0a; g_idx[base+1]=i1a; g_idx[base+2]=i2a;
        g_w[base+0]=w0*inv; g_w[base+1]=w1*inv; g_w[base+2]=w2*inv;

    } else if (blk < 2176) {
        // ---------------- transpose_f2 ----------------
        float (*tt)[33] = (float(*)[33])dsm;
        int idx = blk - 128;
        int s0 = (idx & 63)*32, d0 = ((idx >> 6) & 7)*32, b = idx >> 9;
        int lx = t & 31, ly = t >> 5;
        const float* src = f2 + (size_t)b*D2C*SPTS;
        #pragma unroll
        for (int i = ly; i < 32; i += 8)
            tt[i][lx] = src[(size_t)(d0+i)*SPTS + s0 + lx];
        __syncthreads();
        float* dst = g_f2t + (size_t)b*SPTS*D2C;
        #pragma unroll
        for (int i = ly; i < 32; i += 8)
            dst[(size_t)(s0+i)*D2C + d0 + lx] = tt[lx][i];

    } else if (blk < 4224) {
        // ---------------- copy_f1 -> featB channels [D2, CIN) ----------------
        float (*tile)[33] = (float(*)[33])dsm;
        int idx = blk - 2176;
        int n0 = (idx & 255)*32, d0 = ((idx >> 8) & 1)*64, b = idx >> 9;
        int lx = t & 31, ly = t >> 5;
        const float* src = f1 + ((size_t)b*D1C + d0)*NPTS + n0;
        #pragma unroll
        for (int i = ly; i < 64; i += 8)
            tile[i][lx] = src[(size_t)i*NPTS + lx];
        __syncthreads();
        int g = t & 7, nn = t >> 3;
        int n = b*NPTS + n0 + nn;
        int c = D2C + d0 + g*8;
        float v[8];
        #pragma unroll
        for (int j = 0; j < 8; j++) v[j] = tile[g*8+j][nn];
        char* base = (char*)g_featB + (size_t)n*KH1*2 + (size_t)(c>>6)*256 + (size_t)(c&63)*2;
        store_packHL8(base, base + 128, v);

    } else {
        // ---------------- wexpand (both layers) ----------------
        int i = (blk - 4224)*256 + t;
        float v; __nv_bfloat16* p;
        if (i < CMID*CIN) {
            int m = i / CIN, k = i - m*CIN;
            v = W1[i];
            p = g_W1e + (size_t)m*KH1 + (k>>6)*128 + (k&63);
        } else {
            int j = i - CMID*CIN;
            int m = j / CMID, k = j - m*CMID;
            v = W2[j];
            p = g_W2e + (size_t)m*KH2 + (k>>6)*128 + (k&63);
        }
        uint32_t hi, lo; split_bf(v, hi, lo);
        p[0]  = __ushort_as_bfloat16((unsigned short)hi);
        p[64] = __ushort_as_bfloat16((unsigned short)lo);
    }
}

// ============================================================
// interp: weighted 3-NN -> g_featB channels [0, D2) as hi|lo blocks
// ============================================================
__global__ void interp_kernel() {
    cudaGridDependencySynchronize();
    int t = threadIdx.x;
    int p = blockIdx.x*8 + (t >> 5);
    int kg = t & 31;
    int i0 = __ldg(&g_idx[p*3+0]), i1 = __ldg(&g_idx[p*3+1]), i2 = __ldg(&g_idx[p*3+2]);
    float w0 = __ldg(&g_w[p*3+0]), w1 = __ldg(&g_w[p*3+1]), w2 = __ldg(&g_w[p*3+2]);
    int b = p >> 13;
    const float* f2 = g_f2t + (size_t)b*SPTS*D2C;
    int k0 = kg*8;
    float v[8];
    #pragma unroll
    for (int h = 0; h < 2; h++) {
        float4 a = *(const float4*)&f2[(size_t)i0*D2C + k0 + h*4];
        float4 c = *(const float4*)&f2[(size_t)i1*D2C + k0 + h*4];
        float4 d = *(const float4*)&f2[(size_t)i2*D2C + k0 + h*4];
        v[h*4+0] = w0*a.x + w1*c.x + w2*d.x;
        v[h*4+1] = w0*a.y + w1*c.y + w2*d.y;
        v[h*4+2] = w0*a.z + w1*c.z + w2*d.z;
        v[h*4+3] = w0*a.w + w1*c.w + w2*d.w;
    }
    char* base = (char*)g_featB + (size_t)p*KH1*2 + (size_t)(k0>>6)*256 + (size_t)(k0&63)*2;
    store_packHL8(base, base + 128, v);
}

// ============================================================
// mma.sync GEMM: CTA 256m x 128n, hi|lo 3-product (unchanged mainloop).
// PDL: A (weights, far-upstream) prefetched BEFORE the grid sync.
// ============================================================
#define STAGE_A 65536
#define STAGE_B 32768
#define STAGE_BYTES (STAGE_A + STAGE_B)
#define SMEM_DYN (2*STAGE_BYTES + 128)

template<int KH>
__device__ __forceinline__ void load_A(uint32_t sA,
        const __nv_bfloat16* __restrict__ A, int c, int t) {
    int seg = t & 15, r0 = t >> 4;
    int o = seg*16;
    const char* Ab = (const char*)A + (size_t)c*256 + (size_t)seg*16;
    #pragma unroll
    for (int i = 0; i < 16; i++) {
        int row = r0 + i*16;
        cp16(sA + swz256(row, o), Ab + (size_t)row*KH*2);
    }
}
template<int KH>
__device__ __forceinline__ void load_B(uint32_t sB,
        const __nv_bfloat16* __restrict__ B, int n0, int c, int t) {
    int seg = t & 15, r0 = t >> 4;
    int o = seg*16;
    const char* Bb = (const char*)B + (size_t)n0*KH*2 + (size_t)c*256 + (size_t)seg*16;
    #pragma unroll
    for (int i = 0; i < 8; i++) {
        int row = r0 + i*16;
        cp16(sB + swz256(row, o), Bb + (size_t)row*KH*2);
    }
    asm volatile("cp.async.commit_group;" ::: "memory");
}

template<int MODE>
__global__ void __launch_bounds__(256)
mma_gemm(const float* __restrict__ bias) {
    constexpr int SC = (MODE == 0) ? SC1 : SC2;
    constexpr int KH = SC*128;
    const __nv_bfloat16* A = (MODE == 0) ? g_W1e  : g_W2e;
    const __nv_bfloat16* B = (MODE == 0) ? g_featB : g_y2B;
    float* yT   = (MODE == 0) ? g_y1T : g_y2T;
    float* sacc = (MODE == 0) ? g_sum1 : g_sum2;
    float* qacc = (MODE == 0) ? g_sq1  : g_sq2;

    extern __shared__ char smem[];
    uint32_t sb;
    asm("{ .reg .u64 t; cvta.to.shared.u64 t, %1; cvt.u32.u64 %0, t; }"
        : "=r"(sb) : "l"(smem));
    uint32_t base = (sb + 127u) & ~127u;
    uint32_t sA0 = base,                sB0 = base + STAGE_A;
    uint32_t sA1 = base + STAGE_BYTES,  sB1 = sA1 + STAGE_A;
    float* stage = (float*)(smem + (base - sb));

    int t = threadIdx.x, wid = t >> 5, lane = t & 31;
    int wm = wid >> 1, wn = wid & 1;
    int n0 = blockIdx.x*128;
    int m0w = wm*64, n0w = wn*64;

    float acc[4][8][4];
    #pragma unroll
    for (int i = 0; i < 4; i++)
        #pragma unroll
        for (int j = 0; j < 8; j++)
            #pragma unroll
            for (int e = 0; e < 4; e++) acc[i][j][e] = 0.f;

    int laneRow = lane & 15, laneHi = lane >> 4;

    // prologue: weights (written >=2 kernels upstream) prefetch before sync
    load_A<KH>(sA0, A, 0, t);
    load_A<KH>(sA1, A, 1, t);
    cudaGridDependencySynchronize();
    load_B<KH>(sB0, B, n0, 0, t);   // commits group {A0,A1,B0}
    load_B<KH>(sB1, B, n0, 1, t);   // commits group {B1}

    for (int c = 0; c < SC; c++) {
        if (c + 1 < SC) asm volatile("cp.async.wait_group 1;" ::: "memory");
        else            asm volatile("cp.async.wait_group 0;" ::: "memory");
        __syncthreads();
        uint32_t curA = (c & 1) ? sA1 : sA0;
        uint32_t curB = (c & 1) ? sB1 : sB0;

        #pragma unroll
        for (int ks = 0; ks < 4; ks++) {
            int o_hi = (2*ks + laneHi)*16;
            int o_lo = 128 + o_hi;
            uint32_t ah[4][4], bh[4][4], bl[4][4], al[4][4];
            #pragma unroll
            for (int mi = 0; mi < 4; mi++) {
                int row = m0w + 16*mi + laneRow;
                ldm4(ah[mi], curA + swz256(row, o_hi));
            }
            #pragma unroll
            for (int nj = 0; nj < 4; nj++) {
                int row = n0w + 16*nj + laneRow;
                ldm4(bh[nj], curB + swz256(row, o_hi));
            }
            #pragma unroll
            for (int mi = 0; mi < 4; mi++)
                #pragma unroll
                for (int f = 0; f < 8; f++)
                    mma16816(acc[mi][f], ah[mi], bh[f>>1][f&1], bh[f>>1][(f&1)+2]);
            #pragma unroll
            for (int nj = 0; nj < 4; nj++) {
                int row = n0w + 16*nj + laneRow;
                ldm4(bl[nj], curB + swz256(row, o_lo));
            }
            #pragma unroll
            for (int mi = 0; mi < 4; mi++)
                #pragma unroll
                for (int f = 0; f < 8; f++)
                    mma16816(acc[mi][f], ah[mi], bl[f>>1][f&1], bl[f>>1][(f&1)+2]);
            #pragma unroll
            for (int mi = 0; mi < 4; mi++) {
                int row = m0w + 16*mi + laneRow;
                ldm4(al[mi], curA + swz256(row, o_lo));
            }
            #pragma unroll
            for (int mi = 0; mi < 4; mi++)
                #pragma unroll
                for (int f = 0; f < 8; f++)
                    mma16816(acc[mi][f], al[mi], bh[f>>1][f&1], bh[f>>1][(f&1)+2]);
        }
        __syncthreads();
        if (c + 2 < SC) {
            uint32_t nA = (c & 1) ? sA1 : sA0;
            uint32_t nB = (c & 1) ? sB1 : sB0;
            load_A<KH>(nA, A, c + 2, t);
            load_B<KH>(nB, B, n0, c + 2, t);
        }
    }
    __syncthreads();

    // ---- epilogue: stage [n(128)][m(256)] fp32, pad 260 ----
    {
        int q = lane & 3, r = lane >> 2;
        #pragma unroll
        for (int mi = 0; mi < 4; mi++) {
            int m_l = m0w + 16*mi + r;
            #pragma unroll
            for (int f = 0; f < 8; f++) {
                int n_l = n0w + 8*f + 2*q;
                stage[(size_t)n_l*260 + m_l]          = acc[mi][f][0];
                stage[(size_t)(n_l+1)*260 + m_l]      = acc[mi][f][1];
                stage[(size_t)n_l*260 + m_l + 8]      = acc[mi][f][2];
                stage[(size_t)(n_l+1)*260 + m_l + 8]  = acc[mi][f][3];
            }
        }
    }
    __syncthreads();

    #pragma unroll 4
    for (int idx = t; idx < 128*64; idx += 256) {
        int n_l = idx >> 6, m4 = idx & 63;
        float4 bb = __ldg((const float4*)&bias[m4*4]);
        float* sp = &stage[(size_t)n_l*260 + m4*4];
        float4 v;
        v.x = sp[0] + bb.x; v.y = sp[1] + bb.y;
        v.z = sp[2] + bb.z; v.w = sp[3] + bb.w;
        *(float4*)&yT[(size_t)(n0 + n_l)*256 + m4*4] = v;
    }

    {
        float bb = __ldg(&bias[t]);
        float s = 0.f, q2 = 0.f;
        #pragma unroll 4
        for (int j = 0; j < 128; j++) {
            float v = stage[(size_t)j*260 + t] + bb;
            s += v; q2 += v*v;
        }
        atomicAdd(&sacc[t], s);
        atomicAdd(&qacc[t], q2);
    }
}

// ============================================================
// prep2: BN1 affine in-block, relu(bn1(y1)) -> hi|lo bf16; 2 points/thread
// ============================================================
__global__ void prep2(const float* __restrict__ g, const float* __restrict__ beta) {
    cudaGridDependencySynchronize();
    __shared__ float ssc[CMID], ssh[CMID];
    int t = threadIdx.x;
    {
        float mean = g_sum1[t] * (1.0f/(float)BNT);
        float var  = g_sq1[t]  * (1.0f/(float)BNT) - mean*mean;
        float r = rsqrtf(var + 1e-5f);
        float sc = g[t]*r;
        ssc[t] = sc;
        ssh[t] = beta[t] - mean*sc;
    }
    __syncthreads();
    int gi = blockIdx.x*256 + t;          // grid 2048
    int np = gi >> 5, kg = gi & 31, k0 = kg*8;
    int n0 = np*2;
    float4 ya0 = *(const float4*)&g_y1T[(size_t)n0*CMID + k0];
    float4 ya1 = *(const float4*)&g_y1T[(size_t)n0*CMID + k0 + 4];
    float4 yb0 = *(const float4*)&g_y1T[(size_t)(n0+1)*CMID + k0];
    float4 yb1 = *(const float4*)&g_y1T[(size_t)(n0+1)*CMID + k0 + 4];
    float sc0 = ssc[k0+0], sh0 = ssh[k0+0], sc1 = ssc[k0+1], sh1 = ssh[k0+1];
    float sc2 = ssc[k0+2], sh2 = ssh[k0+2], sc3 = ssc[k0+3], sh3 = ssh[k0+3];
    float sc4 = ssc[k0+4], sh4 = ssh[k0+4], sc5 = ssc[k0+5], sh5 = ssh[k0+5];
    float sc6 = ssc[k0+6], sh6 = ssh[k0+6], sc7 = ssc[k0+7], sh7 = ssh[k0+7];
    float va[8], vb[8];
    va[0]=fmaxf(ya0.x*sc0+sh0,0.f); va[1]=fmaxf(ya0.y*sc1+sh1,0.f);
    va[2]=fmaxf(ya0.z*sc2+sh2,0.f); va[3]=fmaxf(ya0.w*sc3+sh3,0.f);
    va[4]=fmaxf(ya1.x*sc4+sh4,0.f); va[5]=fmaxf(ya1.y*sc5+sh5,0.f);
    va[6]=fmaxf(ya1.z*sc6+sh6,0.f); va[7]=fmaxf(ya1.w*sc7+sh7,0.f);
    vb[0]=fmaxf(yb0.x*sc0+sh0,0.f); vb[1]=fmaxf(yb0.y*sc1+sh1,0.f);
    vb[2]=fmaxf(yb0.z*sc2+sh2,0.f); vb[3]=fmaxf(yb0.w*sc3+sh3,0.f);
    vb[4]=fmaxf(yb1.x*sc4+sh4,0.f); vb[5]=fmaxf(yb1.y*sc5+sh5,0.f);
    vb[6]=fmaxf(yb1.z*sc6+sh6,0.f); vb[7]=fmaxf(yb1.w*sc7+sh7,0.f);
    char* ba = (char*)g_y2B + (size_t)n0*KH2*2 + (size_t)(k0>>6)*256 + (size_t)(k0&63)*2;
    char* bbb = ba + (size_t)KH2*2;
    store_packHL8(ba, ba + 128, va);
    store_packHL8(bbb, bbb + 128, vb);
}

// ============================================================
// final: BN2 affine in-block, y2T [n][m] -> out [b][m][n] + ReLU
// ============================================================
__global__ void final_out(float* __restrict__ out,
                          const float* __restrict__ g, const float* __restrict__ beta) {
    cudaGridDependencySynchronize();
    __shared__ float tile[32][33];
    __shared__ float ssc[32], ssh[32];
    int b = blockIdx.z, m0 = blockIdx.y*32, n0 = blockIdx.x*32;
    int lx = threadIdx.x, ly = threadIdx.y;
    if (ly == 0) {
        int m = m0 + lx;
        float mean = g_sum2[m] * (1.0f/(float)BNT);
        float var  = g_sq2[m]  * (1.0f/(float)BNT) - mean*mean;
        float r = rsqrtf(var + 1e-5f);
        float sc = g[m]*r;
        ssc[lx] = sc;
        ssh[lx] = beta[m] - mean*sc;
    }
    #pragma unroll
    for (int i = ly; i < 32; i += 8)
        tile[i][lx] = g_y2T[(size_t)(b*NPTS + n0 + i)*COUT + m0 + lx];
    __syncthreads();
    #pragma unroll
    for (int i = ly; i < 32; i += 8) {
        float v = tile[lx][i]*ssc[i] + ssh[i];
        out[((size_t)b*COUT + m0 + i)*NPTS + n0 + lx] = fmaxf(v, 0.f);
    }
}

// ============================================================
extern "C" void kernel_launch(void* const* d_in, const int* in_sizes, int n_in,
                              void* d_out, int out_size) {
    const float* pos1 = (const float*)d_in[0];
    const float* pos2 = (const float*)d_in[1];
    const float* f1   = (const float*)d_in[2];
    const float* f2   = (const float*)d_in[3];
    const float* W1   = (const float*)d_in[4];
    const float* b1   = (const float*)d_in[5];
    const float* g1   = (const float*)d_in[6];
    const float* be1  = (const float*)d_in[7];
    const float* W2   = (const float*)d_in[8];
    const float* b2   = (const float*)d_in[9];
    const float* g2   = (const float*)d_in[10];
    const float* be2  = (const float*)d_in[11];
    float* out = (float*)d_out;

    cudaFuncSetAttribute(mma_gemm<0>, cudaFuncAttributeMaxDynamicSharedMemorySize, SMEM_DYN);
    cudaFuncSetAttribute(mma_gemm<1>, cudaFuncAttributeMaxDynamicSharedMemorySize, SMEM_DYN);

    prep_all<<<4864, 256, 32768>>>(pos1, pos2, f2, f1, W1, W2);

    cudaLaunchAttribute at;
    at.id = cudaLaunchAttributeProgrammaticStreamSerialization;
    at.val.programmaticStreamSerializationAllowed = 1;
    cudaLaunchConfig_t cfg = {};
    cfg.attrs = &at; cfg.numAttrs = 1; cfg.stream = 0;

    // interp (PDL after prep_all)
    cfg.gridDim = dim3(BNT/8); cfg.blockDim = dim3(256); cfg.dynamicSmemBytes = 0;
    cudaLaunchKernelExC(&cfg, (const void*)interp_kernel, nullptr);

    // GEMM1 (PDL after interp; weight prefetch pre-sync)
    {
        void* args[] = { (void*)&b1 };
        cfg.gridDim = dim3(BNT/128); cfg.blockDim = dim3(256); cfg.dynamicSmemBytes = SMEM_DYN;
        cudaLaunchKernelExC(&cfg, (const void*)mma_gemm<0>, args);
    }
    // prep2 (PDL after GEMM1)
    {
        void* args[] = { (void*)&g1, (void*)&be1 };
        cfg.gridDim = dim3((BNT*16)/256); cfg.blockDim = dim3(256); cfg.dynamicSmemBytes = 0;
        cudaLaunchKernelExC(&cfg, (const void*)prep2, args);
    }
    // GEMM2 (PDL after prep2; weight prefetch pre-sync)
    {
        void* args[] = { (void*)&b2 };
        cfg.gridDim = dim3(BNT/128); cfg.blockDim = dim3(256); cfg.dynamicSmemBytes = SMEM_DYN;
        cudaLaunchKernelExC(&cfg, (const void*)mma_gemm<1>, args);
    }
    // final (PDL after GEMM2)
    {
        void* args[] = { (void*)&out, (void*)&g2, (void*)&be2 };
        cfg.gridDim = dim3(NPTS/32, COUT/32, BB); cfg.blockDim = dim3(32, 8); cfg.dynamicSmemBytes = 0;
        cudaLaunchKernelExC(&cfg, (const void*)final_out, args);
    }
}